// round 1
// baseline (speedup 1.0000x reference)
#include <cuda_runtime.h>

#define TAU_F 0.1f
#define GROMOV_ITERS 15
#define SINK_ITERS 15
#define N 128
#define S 132   // padded smem row stride (floats)

typedef unsigned long long ull;

__device__ __forceinline__ ull splat2(float x) {
    ull r;
    asm("mov.b64 %0, {%1, %1};" : "=l"(r) : "f"(x));
    return r;
}
__device__ __forceinline__ void ffma2(ull &d, ull a, ull b) {
    asm("fma.rn.f32x2 %0, %1, %2, %0;" : "+l"(d) : "l"(a), "l"(b));
}
union F2U { ull u; float2 f; };

// one k-step of the 8x8 register-tile GEMM (f32x2 packed along columns)
__device__ __forceinline__ void mm8(ull acc[32], const float* __restrict__ aRow,
                                    const float* __restrict__ bRow) {
    float4 a0 = *(const float4*)aRow;
    float4 a1 = *(const float4*)(aRow + 4);
    ull A[8] = { splat2(a0.x), splat2(a0.y), splat2(a0.z), splat2(a0.w),
                 splat2(a1.x), splat2(a1.y), splat2(a1.z), splat2(a1.w) };
    ulonglong2 b01 = *(const ulonglong2*)bRow;
    ulonglong2 b23 = *(const ulonglong2*)(bRow + 4);
    ull B[4] = { b01.x, b01.y, b23.x, b23.y };
#pragma unroll
    for (int r = 0; r < 8; ++r)
#pragma unroll
        for (int c = 0; c < 4; ++c)
            ffma2(acc[r*4 + c], A[r], B[c]);
}

__global__ __launch_bounds__(256, 1)
void gw_kernel(const float* __restrict__ Xg, const float* __restrict__ F1g,
               const float* __restrict__ F2g, const float* __restrict__ Kpg,
               float* __restrict__ outg)
{
    extern __shared__ float sm[];
    float* XT  = sm;                 // [128][S]  X transposed: XT[k][i] = X[i][k]
    float* YB  = XT + N*S;           // [128][S]  Y = X*F2, later Xe
    float* ZB  = YB + N*S;           // [128][S]  Z = X*F2^T
    float* PAN = ZB + N*S;           // [8][S]    staged k-panel (A or B)
    float* ps  = PAN + 8*S;          // [256]     row-sum partials
    float* ps2 = ps + 256;           // [1024]    col-sum partials [8][128]
    float* lu  = ps2 + 1024;         // [128]
    float* rv  = lu + 128;           // [128]
    float* red = rv + 128;           // [32]

    const int t    = threadIdx.x;
    const int b    = blockIdx.x;
    const int tx   = t & 15, ty = t >> 4;
    const int j0   = tx * 8, i0 = ty * 8;
    const int lane = t & 31, w = t >> 5;

    const float* Xb = Xg  + (size_t)b * N * N;
    const float* F1 = F1g + (size_t)b * N * N;
    const float* F2 = F2g + (size_t)b * N * N;
    const float* Kp = Kpg + (size_t)b * N * N;
    float* outb     = outg + (size_t)b * N * N;

    // load X -> XT (transpose)
#pragma unroll
    for (int rep = 0; rep < 16; ++rep) {
        int idx = rep * 256 + t;           // float4 index
        int i = idx >> 5;
        int j4 = (idx & 31) << 2;
        float4 v = *(const float4*)&Xb[i*N + j4];
        XT[(j4+0)*S + i] = v.x;
        XT[(j4+1)*S + i] = v.y;
        XT[(j4+2)*S + i] = v.z;
        XT[(j4+3)*S + i] = v.w;
    }

    ull acc[32];

    for (int it = 0; it < GROMOV_ITERS; ++it) {
        // ---------------- G1: Y = X * F2  (A = XT, B = F2 rows) --------------
#pragma unroll
        for (int q = 0; q < 32; ++q) acc[q] = 0ull;
        for (int p = 0; p < 16; ++p) {
            __syncthreads();
            {   // stage 8 rows of F2
                int kk = t >> 5; int j4 = (t & 31) << 2;
                float4 v = *(const float4*)&F2[(p*8 + kk)*N + j4];
                *(float4*)&PAN[kk*S + j4] = v;
            }
            __syncthreads();
            const float* Ab = XT + p*8*S + i0;
            const float* Bb = PAN + j0;
#pragma unroll
            for (int kk = 0; kk < 8; ++kk)
                mm8(acc, Ab + kk*S, Bb + kk*S);
        }
#pragma unroll
        for (int r = 0; r < 8; ++r) {
            ulonglong2 s0; s0.x = acc[r*4+0]; s0.y = acc[r*4+1];
            ulonglong2 s1; s1.x = acc[r*4+2]; s1.y = acc[r*4+3];
            *(ulonglong2*)&YB[(i0+r)*S + j0]     = s0;
            *(ulonglong2*)&YB[(i0+r)*S + j0 + 4] = s1;
        }

        // ---------------- G2: Z = X * F2^T  (B panel = F2 column slice) ------
#pragma unroll
        for (int q = 0; q < 32; ++q) acc[q] = 0ull;
        for (int p = 0; p < 16; ++p) {
            __syncthreads();
            {   // stage transposed slice: PAN[kk][i] = F2[i][p*8+kk]
                int i = t >> 1; int c4 = (t & 1) << 2;
                float4 v = *(const float4*)&F2[i*N + p*8 + c4];
                PAN[(c4+0)*S + i] = v.x;
                PAN[(c4+1)*S + i] = v.y;
                PAN[(c4+2)*S + i] = v.z;
                PAN[(c4+3)*S + i] = v.w;
            }
            __syncthreads();
            const float* Ab = XT + p*8*S + i0;
            const float* Bb = PAN + j0;
#pragma unroll
            for (int kk = 0; kk < 8; ++kk)
                mm8(acc, Ab + kk*S, Bb + kk*S);
        }
#pragma unroll
        for (int r = 0; r < 8; ++r) {
            ulonglong2 s0; s0.x = acc[r*4+0]; s0.y = acc[r*4+1];
            ulonglong2 s1; s1.x = acc[r*4+2]; s1.y = acc[r*4+3];
            *(ulonglong2*)&ZB[(i0+r)*S + j0]     = s0;
            *(ulonglong2*)&ZB[(i0+r)*S + j0 + 4] = s1;
        }

        // ---------------- C = Kp + F1*Y + F1^T*Z  (C stays in registers) -----
#pragma unroll
        for (int r = 0; r < 8; ++r) {
            const ulonglong2* kp = (const ulonglong2*)&Kp[(i0+r)*N + j0];
            ulonglong2 k0v = kp[0], k1v = kp[1];
            acc[r*4+0] = k0v.x; acc[r*4+1] = k0v.y;
            acc[r*4+2] = k1v.x; acc[r*4+3] = k1v.y;
        }
        // G3: += F1 * Y   (A panel = F1 column slice transposed, B = YB)
        for (int p = 0; p < 16; ++p) {
            __syncthreads();
            {   // PAN[kk][i] = F1[i][p*8+kk]
                int i = t >> 1; int c4 = (t & 1) << 2;
                float4 v = *(const float4*)&F1[i*N + p*8 + c4];
                PAN[(c4+0)*S + i] = v.x;
                PAN[(c4+1)*S + i] = v.y;
                PAN[(c4+2)*S + i] = v.z;
                PAN[(c4+3)*S + i] = v.w;
            }
            __syncthreads();
            const float* Ab = PAN + i0;
            const float* Bb = YB + p*8*S + j0;
#pragma unroll
            for (int kk = 0; kk < 8; ++kk)
                mm8(acc, Ab + kk*S, Bb + kk*S);
        }
        // G4: += F1^T * Z  (A panel = F1 rows, B = ZB)
        for (int p = 0; p < 16; ++p) {
            __syncthreads();
            {   // PAN[kk][i] = F1[p*8+kk][i]
                int kk = t >> 5; int j4 = (t & 31) << 2;
                float4 v = *(const float4*)&F1[(p*8 + kk)*N + j4];
                *(float4*)&PAN[kk*S + j4] = v;
            }
            __syncthreads();
            const float* Ab = PAN + i0;
            const float* Bb = ZB + p*8*S + j0;
#pragma unroll
            for (int kk = 0; kk < 8; ++kk)
                mm8(acc, Ab + kk*S, Bb + kk*S);
        }

        // ---------------- L-inf norm of C (block max reduce) -----------------
        float m = 0.0f;
#pragma unroll
        for (int q = 0; q < 32; ++q) {
            F2U u; u.u = acc[q];
            m = fmaxf(m, fmaxf(fabsf(u.f.x), fabsf(u.f.y)));
        }
#pragma unroll
        for (int off = 16; off > 0; off >>= 1)
            m = fmaxf(m, __shfl_xor_sync(0xffffffffu, m, off));
        if (lane == 0) red[w] = m;
        __syncthreads();
        if (t == 0) {
            float n = red[0];
#pragma unroll
            for (int q = 1; q < 8; ++q) n = fmaxf(n, red[q]);
            red[8] = 1.0f / (n * TAU_F);
        }
        __syncthreads();
        const float scale = red[8];

        // ---------------- Xe = exp(C * scale) -> YB --------------------------
#pragma unroll
        for (int r = 0; r < 8; ++r) {
            F2U u0, u1, u2, u3;
            u0.u = acc[r*4+0]; u1.u = acc[r*4+1];
            u2.u = acc[r*4+2]; u3.u = acc[r*4+3];
            float4 e0, e1;
            e0.x = __expf(u0.f.x * scale); e0.y = __expf(u0.f.y * scale);
            e0.z = __expf(u1.f.x * scale); e0.w = __expf(u1.f.y * scale);
            e1.x = __expf(u2.f.x * scale); e1.y = __expf(u2.f.y * scale);
            e1.z = __expf(u3.f.x * scale); e1.w = __expf(u3.f.y * scale);
            *(float4*)&YB[(i0+r)*S + j0]     = e0;
            *(float4*)&YB[(i0+r)*S + j0 + 4] = e1;
        }
        if (t < 128) rv[t] = 1.0f;
        __syncthreads();

        // ---------------- partial Sinkhorn (15 iters) ------------------------
        for (int sit = 0; sit < SINK_ITERS; ++sit) {
            {   // lu[i] = 1 / sum_j Xe[i][j]*rv[j]
                int i = t >> 1, h = t & 1;
                const float4* xe = (const float4*)&YB[i*S + h*64];
                const float4* rb = (const float4*)&rv[h*64];
                float ssum = 0.0f;
#pragma unroll
                for (int q = 0; q < 16; ++q) {
                    float4 x = xe[q], r4 = rb[q];
                    ssum += x.x*r4.x + x.y*r4.y + x.z*r4.z + x.w*r4.w;
                }
                ps[t] = ssum;
            }
            __syncthreads();
            if (t < 128) lu[t] = 1.0f / (ps[2*t] + ps[2*t+1]);
            __syncthreads();
            {   // colsum[j] = sum_i Xe[i][j]*lu[i]  (warp w covers rows w*16..)
                int jb = lane << 2;
                float4 sv; sv.x = sv.y = sv.z = sv.w = 0.0f;
#pragma unroll
                for (int q = 0; q < 16; ++q) {
                    int i = w*16 + q;
                    float l = lu[i];
                    float4 x = *(const float4*)&YB[i*S + jb];
                    sv.x += l*x.x; sv.y += l*x.y; sv.z += l*x.z; sv.w += l*x.w;
                }
                *(float4*)&ps2[w*128 + jb] = sv;
            }
            __syncthreads();
            if (t < 128) {
                float ssum = 0.0f;
#pragma unroll
                for (int q = 0; q < 8; ++q) ssum += ps2[q*128 + t];
                rv[t] = fminf(1.0f / ssum, 1.0f);
            }
            __syncthreads();
        }

        // ---------------- X = lu * Xe * rv^T ---------------------------------
        if (it + 1 < GROMOV_ITERS) {
            int i = t >> 1, h = t & 1;
            float l = lu[i];
#pragma unroll
            for (int q = 0; q < 16; ++q) {
                int j = h*64 + q*4;
                float4 x  = *(const float4*)&YB[i*S + j];
                float4 r4 = *(const float4*)&rv[j];
                XT[(j+0)*S + i] = l * x.x * r4.x;
                XT[(j+1)*S + i] = l * x.y * r4.y;
                XT[(j+2)*S + i] = l * x.z * r4.z;
                XT[(j+3)*S + i] = l * x.w * r4.w;
            }
        } else {
#pragma unroll
            for (int rep = 0; rep < 16; ++rep) {
                int idx = rep * 256 + t;
                int i = idx >> 5; int j4 = (idx & 31) << 2;
                float l = lu[i];
                float4 x  = *(const float4*)&YB[i*S + j4];
                float4 r4 = *(const float4*)&rv[j4];
                float4 o;
                o.x = l * x.x * r4.x; o.y = l * x.y * r4.y;
                o.z = l * x.z * r4.z; o.w = l * x.w * r4.w;
                *(float4*)&outb[i*N + j4] = o;
            }
        }
    }
}

extern "C" void kernel_launch(void* const* d_in, const int* in_sizes, int n_in,
                              void* d_out, int out_size)
{
    const float* X  = (const float*)d_in[0];
    const float* F1 = (const float*)d_in[1];
    const float* F2 = (const float*)d_in[2];
    const float* Kp = (const float*)d_in[3];
    float* out = (float*)d_out;

    int bs = in_sizes[0] / (N * N);   // 2048

    size_t smem = (size_t)(3*N*S + 8*S + 256 + 1024 + 128 + 128 + 32) * sizeof(float);
    cudaFuncSetAttribute(gw_kernel, cudaFuncAttributeMaxDynamicSharedMemorySize, (int)smem);
    gw_kernel<<<bs, 256, smem>>>(X, F1, F2, Kp, out);
}

// round 2
// speedup vs baseline: 1.2914x; 1.2914x over previous
#include <cuda_runtime.h>

#define TAU_F 0.1f
#define GROMOV_ITERS 15
#define SINK_ITERS 15
#define N 128
#define S 132          // padded smem row stride (floats), mult of 4
#define THREADS 512

typedef unsigned long long ull;

__device__ __forceinline__ ull splat2(float x) {
    ull r; asm("mov.b64 %0, {%1, %1};" : "=l"(r) : "f"(x)); return r;
}
__device__ __forceinline__ void ffma2(ull &d, ull a, ull b) {
    asm("fma.rn.f32x2 %0, %1, %2, %0;" : "+l"(d) : "l"(a), "l"(b));
}
__device__ __forceinline__ ull mul2(ull a, ull b) {
    ull d; asm("mul.rn.f32x2 %0, %1, %2;" : "=l"(d) : "l"(a), "l"(b)); return d;
}
union F2U { ull u; float2 f; };

// 4x8 tile k-step: A 4 consecutive floats at aP, B cols [j0,j0+4) at bP and
// [j0+64,j0+68) at bP+64. acc[r*4+c]: c=0,1 -> cols j0+2c ; c=2,3 -> j0+64+2(c-2)
__device__ __forceinline__ void mm4(ull* acc, const float* aP, const float* bP) {
    float4 a = *(const float4*)aP;
    ull A0 = splat2(a.x), A1 = splat2(a.y), A2 = splat2(a.z), A3 = splat2(a.w);
    ulonglong2 bx = *(const ulonglong2*)bP;
    ulonglong2 by = *(const ulonglong2*)(bP + 64);
    ull B0 = bx.x, B1 = bx.y, B2 = by.x, B3 = by.y;
    ffma2(acc[0],  A0, B0); ffma2(acc[1],  A0, B1); ffma2(acc[2],  A0, B2); ffma2(acc[3],  A0, B3);
    ffma2(acc[4],  A1, B0); ffma2(acc[5],  A1, B1); ffma2(acc[6],  A1, B2); ffma2(acc[7],  A1, B3);
    ffma2(acc[8],  A2, B0); ffma2(acc[9],  A2, B1); ffma2(acc[10], A2, B2); ffma2(acc[11], A2, B3);
    ffma2(acc[12], A3, B0); ffma2(acc[13], A3, B1); ffma2(acc[14], A3, B2); ffma2(acc[15], A3, B3);
}

// panel staging, pattern R (rows): PAN[kk][j] = src[p*8+kk][j]
__device__ __forceinline__ float2 ldgR(const float* __restrict__ src, int p, int t) {
    int kk = t >> 6, j2 = (t & 63) << 1;
    return *(const float2*)&src[(p*8 + kk)*N + j2];
}
__device__ __forceinline__ void stsR(float* pan, float2 v, int t) {
    int kk = t >> 6, j2 = (t & 63) << 1;
    *(float2*)&pan[kk*S + j2] = v;
}
// pattern T (transposed): PAN[c][i] = src[i][p*8+c]
__device__ __forceinline__ float2 ldgT(const float* __restrict__ src, int p, int t) {
    int i = t >> 2, c2 = (t & 3) << 1;
    return *(const float2*)&src[i*N + p*8 + c2];
}
__device__ __forceinline__ void stsT(float* pan, float2 v, int t) {
    int i = t >> 2, c2 = (t & 3) << 1;
    pan[c2*S + i]       = v.x;
    pan[(c2+1)*S + i]   = v.y;
}

// One 128x128x128 GEMM with double-buffered panel staging, one sync per panel.
// A_PANEL: A operand comes from the staged panel (B = Wb big buffer);
// otherwise A = XT and B = staged panel. PAT_T selects transposed staging.
template<bool A_PANEL, bool PAT_T>
__device__ __forceinline__ void run_gemm(ull* acc, const float* __restrict__ src,
        const float* __restrict__ XT, const float* __restrict__ Wb,
        float* __restrict__ PAN, int t, int i0, int j0)
{
    float2 r = PAT_T ? ldgT(src, 0, t) : ldgR(src, 0, t);
    __syncthreads();                      // prior readers of PAN / writers of Wb done
    if (PAT_T) stsT(PAN, r, t); else stsR(PAN, r, t);
    r = PAT_T ? ldgT(src, 1, t) : ldgR(src, 1, t);
#pragma unroll 1
    for (int p = 0; p < 16; ++p) {
        __syncthreads();                  // STS(p) visible; compute(p-1) done
        float* pc = PAN + (p & 1)*8*S;
        if (p + 1 < 16) {
            float* pn = PAN + ((p + 1) & 1)*8*S;
            if (PAT_T) stsT(pn, r, t); else stsR(pn, r, t);
            if (p + 2 < 16) r = PAT_T ? ldgT(src, p + 2, t) : ldgR(src, p + 2, t);
        }
        const float* aP = A_PANEL ? (pc + i0) : (XT + p*8*S + i0);
        const float* bP = A_PANEL ? (Wb + p*8*S + j0) : (pc + j0);
#pragma unroll
        for (int kk = 0; kk < 8; ++kk)
            mm4(acc, aP + kk*S, bP + kk*S);
    }
}

__global__ __launch_bounds__(THREADS, 1)
void gw_kernel(const float* __restrict__ Xg, const float* __restrict__ F1g,
               const float* __restrict__ F2g, const float* __restrict__ Kpg,
               float* __restrict__ outg)
{
    extern __shared__ float sm[];
    float* XT  = sm;                 // [128][S] X transposed: XT[k][i] = X[i][k]
    float* W   = XT + N*S;           // [128][S] work buffer: Y, then Z, then lu*Xe*rv
    float* PAN = W + N*S;            // [2][8][S] double-buffered k-panel
    float* psc = PAN + 2*8*S;        // [32][S]  col-sum partials per ty-group
    float* rv  = psc + 32*S;         // [128]
    float* red = rv + 128;           // [17]

    const int t    = threadIdx.x;
    const int tx   = t & 15, ty = t >> 4;
    const int j0   = tx * 4, i0 = ty * 4;
    const int lane = t & 31, w = t >> 5;
    const int b    = blockIdx.x;

    const float* Xb = Xg  + (size_t)b * N * N;
    const float* F1 = F1g + (size_t)b * N * N;
    const float* F2 = F2g + (size_t)b * N * N;
    const float* Kp = Kpg + (size_t)b * N * N;
    float* outb     = outg + (size_t)b * N * N;

    // ---- initial transpose X -> XT (conflict-free scatter) ----
    {
        int ti = t & 127, tg = t >> 7;      // ti row, tg col-group (32 cols)
#pragma unroll
        for (int c = 0; c < 8; ++c) {
            float4 v = *(const float4*)&Xb[ti*N + tg*32 + c*4];
            int jb = tg*32 + c*4;
            XT[(jb+0)*S + ti] = v.x;
            XT[(jb+1)*S + ti] = v.y;
            XT[(jb+2)*S + ti] = v.z;
            XT[(jb+3)*S + ti] = v.w;
        }
    }

    ull accW[16], accC[16];

    for (int it = 0; it < GROMOV_ITERS; ++it) {
        // ---- Phase A: Y = X*F2 (B panel = F2 rows) ----
#pragma unroll
        for (int q = 0; q < 16; ++q) accW[q] = 0ull;
        run_gemm<false, false>(accW, F2, XT, W, PAN, t, i0, j0);
#pragma unroll
        for (int r = 0; r < 4; ++r) {
            ulonglong2 s0; s0.x = accW[r*4+0]; s0.y = accW[r*4+1];
            ulonglong2 s1; s1.x = accW[r*4+2]; s1.y = accW[r*4+3];
            *(ulonglong2*)&W[(i0+r)*S + j0]      = s0;
            *(ulonglong2*)&W[(i0+r)*S + j0 + 64] = s1;
        }

        // ---- Phase B: C = Kp + F1*Y (A panel = F1^T slices, B = W) ----
#pragma unroll
        for (int r = 0; r < 4; ++r) {
            ulonglong2 k0 = *(const ulonglong2*)&Kp[(i0+r)*N + j0];
            ulonglong2 k1 = *(const ulonglong2*)&Kp[(i0+r)*N + j0 + 64];
            accC[r*4+0] = k0.x; accC[r*4+1] = k0.y;
            accC[r*4+2] = k1.x; accC[r*4+3] = k1.y;
        }
        run_gemm<true, true>(accC, F1, XT, W, PAN, t, i0, j0);

        // ---- Phase C: Z = X*F2^T (B panel = F2^T slices) [accC stays live] ----
#pragma unroll
        for (int q = 0; q < 16; ++q) accW[q] = 0ull;
        run_gemm<false, true>(accW, F2, XT, W, PAN, t, i0, j0);
#pragma unroll
        for (int r = 0; r < 4; ++r) {
            ulonglong2 s0; s0.x = accW[r*4+0]; s0.y = accW[r*4+1];
            ulonglong2 s1; s1.x = accW[r*4+2]; s1.y = accW[r*4+3];
            *(ulonglong2*)&W[(i0+r)*S + j0]      = s0;
            *(ulonglong2*)&W[(i0+r)*S + j0 + 64] = s1;
        }

        // ---- Phase D: C += F1^T*Z (A panel = F1 rows, B = W) ----
        run_gemm<true, false>(accC, F1, XT, W, PAN, t, i0, j0);

        // ---- L-inf norm of C ----
        float m = 0.0f;
#pragma unroll
        for (int q = 0; q < 16; ++q) {
            F2U u; u.u = accC[q];
            m = fmaxf(m, fmaxf(fabsf(u.f.x), fabsf(u.f.y)));
        }
#pragma unroll
        for (int off = 16; off > 0; off >>= 1)
            m = fmaxf(m, __shfl_xor_sync(0xffffffffu, m, off));
        if (lane == 0) red[w] = m;
        __syncthreads();
        if (t == 0) {
            float n = red[0];
#pragma unroll
            for (int q = 1; q < 16; ++q) n = fmaxf(n, red[q]);
            red[16] = __fdividef(1.0f, n * TAU_F);
        }
        __syncthreads();
        const float scale = red[16];

        // ---- Xe = exp(C*scale), kept in registers (reuse accC) ----
#pragma unroll
        for (int q = 0; q < 16; ++q) {
            F2U u; u.u = accC[q];
            u.f.x = __expf(u.f.x * scale);
            u.f.y = __expf(u.f.y * scale);
            accC[q] = u.u;
        }
        if (t < 128) rv[t] = 1.0f;
        __syncthreads();

        // ---- partial Sinkhorn, Xe register-resident ----
        float lu_r[4];
        for (int sit = 0; sit < SINK_ITERS; ++sit) {
            // row sums: lu[i] = 1 / sum_j Xe[i][j]*rv[j]
            ulonglong2 rv0 = *(const ulonglong2*)&rv[j0];
            ulonglong2 rv1 = *(const ulonglong2*)&rv[j0 + 64];
            ull R[4] = { rv0.x, rv0.y, rv1.x, rv1.y };
#pragma unroll
            for (int r = 0; r < 4; ++r) {
                ull s2 = 0ull;
#pragma unroll
                for (int c = 0; c < 4; ++c) ffma2(s2, accC[r*4+c], R[c]);
                F2U u; u.u = s2;
                float s = u.f.x + u.f.y;
#pragma unroll
                for (int off = 1; off < 16; off <<= 1)
                    s += __shfl_xor_sync(0xffffffffu, s, off);
                lu_r[r] = __fdividef(1.0f, s);
            }
            // col partials: cp[j-chunk] = sum_{r in tile} lu[i0+r]*Xe
            ull cp0 = 0, cp1 = 0, cp2 = 0, cp3 = 0;
#pragma unroll
            for (int r = 0; r < 4; ++r) {
                ull L = splat2(lu_r[r]);
                ffma2(cp0, L, accC[r*4+0]);
                ffma2(cp1, L, accC[r*4+1]);
                ffma2(cp2, L, accC[r*4+2]);
                ffma2(cp3, L, accC[r*4+3]);
            }
            { ulonglong2 v; v.x = cp0; v.y = cp1;
              *(ulonglong2*)&psc[ty*S + j0] = v; }
            { ulonglong2 v; v.x = cp2; v.y = cp3;
              *(ulonglong2*)&psc[ty*S + j0 + 64] = v; }
            __syncthreads();
            if (t < 128) {
                float s = 0.0f;
#pragma unroll
                for (int g = 0; g < 32; ++g) s += psc[g*S + t];
                rv[t] = fminf(__fdividef(1.0f, s), 1.0f);
            }
            __syncthreads();
        }

        // ---- X_new = lu * Xe * rv^T ----
        ulonglong2 rv0 = *(const ulonglong2*)&rv[j0];
        ulonglong2 rv1 = *(const ulonglong2*)&rv[j0 + 64];
        ull R[4] = { rv0.x, rv0.y, rv1.x, rv1.y };
        ull P[16];
#pragma unroll
        for (int r = 0; r < 4; ++r) {
            ull L = splat2(lu_r[r]);
#pragma unroll
            for (int c = 0; c < 4; ++c)
                P[r*4+c] = mul2(mul2(L, accC[r*4+c]), R[c]);
        }
        if (it + 1 < GROMOV_ITERS) {
            // store product to W, then transpose W -> XT
#pragma unroll
            for (int r = 0; r < 4; ++r) {
                ulonglong2 s0; s0.x = P[r*4+0]; s0.y = P[r*4+1];
                ulonglong2 s1; s1.x = P[r*4+2]; s1.y = P[r*4+3];
                *(ulonglong2*)&W[(i0+r)*S + j0]      = s0;
                *(ulonglong2*)&W[(i0+r)*S + j0 + 64] = s1;
            }
            __syncthreads();
            int ti = t & 127, tg = t >> 7;
#pragma unroll
            for (int c = 0; c < 8; ++c) {
                float4 v = *(const float4*)&W[ti*S + tg*32 + c*4];
                int jb = tg*32 + c*4;
                XT[(jb+0)*S + ti] = v.x;
                XT[(jb+1)*S + ti] = v.y;
                XT[(jb+2)*S + ti] = v.z;
                XT[(jb+3)*S + ti] = v.w;
            }
            // visibility guaranteed by next phase-A prologue syncs
        } else {
#pragma unroll
            for (int r = 0; r < 4; ++r) {
                ulonglong2 s0; s0.x = P[r*4+0]; s0.y = P[r*4+1];
                ulonglong2 s1; s1.x = P[r*4+2]; s1.y = P[r*4+3];
                *(ulonglong2*)&outb[(i0+r)*N + j0]      = s0;
                *(ulonglong2*)&outb[(i0+r)*N + j0 + 64] = s1;
            }
        }
    }
}

extern "C" void kernel_launch(void* const* d_in, const int* in_sizes, int n_in,
                              void* d_out, int out_size)
{
    const float* X  = (const float*)d_in[0];
    const float* F1 = (const float*)d_in[1];
    const float* F2 = (const float*)d_in[2];
    const float* Kp = (const float*)d_in[3];
    float* out = (float*)d_out;

    int bs = in_sizes[0] / (N * N);

    size_t smem = (size_t)(2*N*S + 2*8*S + 32*S + 128 + 17 + 15) * sizeof(float);
    cudaFuncSetAttribute(gw_kernel, cudaFuncAttributeMaxDynamicSharedMemorySize, (int)smem);
    gw_kernel<<<bs, THREADS, smem>>>(X, F1, F2, Kp, out);
}

// round 3
// speedup vs baseline: 1.2927x; 1.0010x over previous
#include <cuda_runtime.h>

#define TAU_F 0.1f
#define GROMOV_ITERS 15
#define SINK_ITERS 15
#define N 128
#define S 132          // padded smem row stride (floats), mult of 4
#define THREADS 512

typedef unsigned long long ull;

__device__ __forceinline__ ull splat2(float x) {
    ull r; asm("mov.b64 %0, {%1, %1};" : "=l"(r) : "f"(x)); return r;
}
__device__ __forceinline__ void ffma2(ull &d, ull a, ull b) {
    asm("fma.rn.f32x2 %0, %1, %2, %0;" : "+l"(d) : "l"(a), "l"(b));
}
__device__ __forceinline__ ull mul2(ull a, ull b) {
    ull d; asm("mul.rn.f32x2 %0, %1, %2;" : "=l"(d) : "l"(a), "l"(b)); return d;
}
union F2U { ull u; float2 f; };

// 4x8 tile k-step: A 4 consecutive floats at aP, B cols [j0,j0+4) at bP and
// [j0+64,j0+68) at bP+64. acc[r*4+c]: c=0,1 -> cols j0+2c ; c=2,3 -> j0+64+2(c-2)
__device__ __forceinline__ void mm4(ull* acc, const float* aP, const float* bP) {
    float4 a = *(const float4*)aP;
    ull A0 = splat2(a.x), A1 = splat2(a.y), A2 = splat2(a.z), A3 = splat2(a.w);
    ulonglong2 bx = *(const ulonglong2*)bP;
    ulonglong2 by = *(const ulonglong2*)(bP + 64);
    ull B0 = bx.x, B1 = bx.y, B2 = by.x, B3 = by.y;
    ffma2(acc[0],  A0, B0); ffma2(acc[1],  A0, B1); ffma2(acc[2],  A0, B2); ffma2(acc[3],  A0, B3);
    ffma2(acc[4],  A1, B0); ffma2(acc[5],  A1, B1); ffma2(acc[6],  A1, B2); ffma2(acc[7],  A1, B3);
    ffma2(acc[8],  A2, B0); ffma2(acc[9],  A2, B1); ffma2(acc[10], A2, B2); ffma2(acc[11], A2, B3);
    ffma2(acc[12], A3, B0); ffma2(acc[13], A3, B1); ffma2(acc[14], A3, B2); ffma2(acc[15], A3, B3);
}

// panel staging, pattern R (rows): PAN[kk][j] = src[p*8+kk][j]
__device__ __forceinline__ float2 ldgR(const float* __restrict__ src, int p, int t) {
    int kk = t >> 6, j2 = (t & 63) << 1;
    return *(const float2*)&src[(p*8 + kk)*N + j2];
}
__device__ __forceinline__ void stsR(float* pan, float2 v, int t) {
    int kk = t >> 6, j2 = (t & 63) << 1;
    *(float2*)&pan[kk*S + j2] = v;
}
// pattern T (transposed): PAN[c][i] = src[i][p*8+c]
__device__ __forceinline__ float2 ldgT(const float* __restrict__ src, int p, int t) {
    int i = t >> 2, c2 = (t & 3) << 1;
    return *(const float2*)&src[i*N + p*8 + c2];
}
__device__ __forceinline__ void stsT(float* pan, float2 v, int t) {
    int i = t >> 2, c2 = (t & 3) << 1;
    pan[c2*S + i]       = v.x;
    pan[(c2+1)*S + i]   = v.y;
}

// One 128x128x128 GEMM with double-buffered panel staging, one sync per panel.
// A_PANEL: A operand comes from the staged panel (B = Wb big buffer);
// otherwise A = XT and B = staged panel. PAT_T selects transposed staging.
template<bool A_PANEL, bool PAT_T>
__device__ __forceinline__ void run_gemm(ull* acc, const float* __restrict__ src,
        const float* __restrict__ XT, const float* __restrict__ Wb,
        float* __restrict__ PAN, int t, int i0, int j0)
{
    float2 r = PAT_T ? ldgT(src, 0, t) : ldgR(src, 0, t);
    __syncthreads();                      // prior readers of PAN / writers of Wb done
    if (PAT_T) stsT(PAN, r, t); else stsR(PAN, r, t);
    r = PAT_T ? ldgT(src, 1, t) : ldgR(src, 1, t);
#pragma unroll 1
    for (int p = 0; p < 16; ++p) {
        __syncthreads();                  // STS(p) visible; compute(p-1) done
        float* pc = PAN + (p & 1)*8*S;
        if (p + 1 < 16) {
            float* pn = PAN + ((p + 1) & 1)*8*S;
            if (PAT_T) stsT(pn, r, t); else stsR(pn, r, t);
            if (p + 2 < 16) r = PAT_T ? ldgT(src, p + 2, t) : ldgR(src, p + 2, t);
        }
        const float* aP = A_PANEL ? (pc + i0) : (XT + p*8*S + i0);
        const float* bP = A_PANEL ? (Wb + p*8*S + j0) : (pc + j0);
#pragma unroll
        for (int kk = 0; kk < 8; ++kk)
            mm4(acc, aP + kk*S, bP + kk*S);
    }
}

__global__ __launch_bounds__(THREADS, 1)
void gw_kernel(const float* __restrict__ Xg, const float* __restrict__ F1g,
               const float* __restrict__ F2g, const float* __restrict__ Kpg,
               float* __restrict__ outg)
{
    extern __shared__ float sm[];
    float* XT  = sm;                 // [128][S] X transposed: XT[k][i] = X[i][k]
    float* W   = XT + N*S;           // [128][S] work buffer: Y, then Z, then lu*Xe*rv
    float* PAN = W + N*S;            // [2][8][S] double-buffered k-panel
    float* psc = PAN + 2*8*S;        // [32][S]  col-sum partials per ty-group
    float* rv  = psc + 32*S;         // [128]
    float* red = rv + 128;           // [17]

    const int t    = threadIdx.x;
    const int tx   = t & 15, ty = t >> 4;
    const int j0   = tx * 4, i0 = ty * 4;
    const int lane = t & 31, w = t >> 5;
    const int b    = blockIdx.x;

    const float* Xb = Xg  + (size_t)b * N * N;
    const float* F1 = F1g + (size_t)b * N * N;
    const float* F2 = F2g + (size_t)b * N * N;
    const float* Kp = Kpg + (size_t)b * N * N;
    float* outb     = outg + (size_t)b * N * N;

    // ---- initial transpose X -> XT (conflict-free scatter) ----
    {
        int ti = t & 127, tg = t >> 7;      // ti row, tg col-group (32 cols)
#pragma unroll
        for (int c = 0; c < 8; ++c) {
            float4 v = *(const float4*)&Xb[ti*N + tg*32 + c*4];
            int jb = tg*32 + c*4;
            XT[(jb+0)*S + ti] = v.x;
            XT[(jb+1)*S + ti] = v.y;
            XT[(jb+2)*S + ti] = v.z;
            XT[(jb+3)*S + ti] = v.w;
        }
    }

    ull accW[16], accC[16];

    for (int it = 0; it < GROMOV_ITERS; ++it) {
        // ---- Phase A: Y = X*F2 (B panel = F2 rows) ----
#pragma unroll
        for (int q = 0; q < 16; ++q) accW[q] = 0ull;
        run_gemm<false, false>(accW, F2, XT, W, PAN, t, i0, j0);
#pragma unroll
        for (int r = 0; r < 4; ++r) {
            ulonglong2 s0; s0.x = accW[r*4+0]; s0.y = accW[r*4+1];
            ulonglong2 s1; s1.x = accW[r*4+2]; s1.y = accW[r*4+3];
            *(ulonglong2*)&W[(i0+r)*S + j0]      = s0;
            *(ulonglong2*)&W[(i0+r)*S + j0 + 64] = s1;
        }

        // ---- Phase B: C = Kp + F1*Y (A panel = F1^T slices, B = W) ----
#pragma unroll
        for (int r = 0; r < 4; ++r) {
            ulonglong2 k0 = *(const ulonglong2*)&Kp[(i0+r)*N + j0];
            ulonglong2 k1 = *(const ulonglong2*)&Kp[(i0+r)*N + j0 + 64];
            accC[r*4+0] = k0.x; accC[r*4+1] = k0.y;
            accC[r*4+2] = k1.x; accC[r*4+3] = k1.y;
        }
        run_gemm<true, true>(accC, F1, XT, W, PAN, t, i0, j0);

        // ---- Phase C: Z = X*F2^T (B panel = F2^T slices) [accC stays live] ----
#pragma unroll
        for (int q = 0; q < 16; ++q) accW[q] = 0ull;
        run_gemm<false, true>(accW, F2, XT, W, PAN, t, i0, j0);
#pragma unroll
        for (int r = 0; r < 4; ++r) {
            ulonglong2 s0; s0.x = accW[r*4+0]; s0.y = accW[r*4+1];
            ulonglong2 s1; s1.x = accW[r*4+2]; s1.y = accW[r*4+3];
            *(ulonglong2*)&W[(i0+r)*S + j0]      = s0;
            *(ulonglong2*)&W[(i0+r)*S + j0 + 64] = s1;
        }

        // ---- Phase D: C += F1^T*Z (A panel = F1 rows, B = W) ----
        run_gemm<true, false>(accC, F1, XT, W, PAN, t, i0, j0);

        // ---- L-inf norm of C ----
        float m = 0.0f;
#pragma unroll
        for (int q = 0; q < 16; ++q) {
            F2U u; u.u = accC[q];
            m = fmaxf(m, fmaxf(fabsf(u.f.x), fabsf(u.f.y)));
        }
#pragma unroll
        for (int off = 16; off > 0; off >>= 1)
            m = fmaxf(m, __shfl_xor_sync(0xffffffffu, m, off));
        if (lane == 0) red[w] = m;
        __syncthreads();
        if (t == 0) {
            float n = red[0];
#pragma unroll
            for (int q = 1; q < 16; ++q) n = fmaxf(n, red[q]);
            red[16] = __fdividef(1.0f, n * TAU_F);
        }
        __syncthreads();
        const float scale = red[16];

        // ---- Xe = exp(C*scale), kept in registers (reuse accC) ----
#pragma unroll
        for (int q = 0; q < 16; ++q) {
            F2U u; u.u = accC[q];
            u.f.x = __expf(u.f.x * scale);
            u.f.y = __expf(u.f.y * scale);
            accC[q] = u.u;
        }
        if (t < 128) rv[t] = 1.0f;
        __syncthreads();

        // ---- partial Sinkhorn, Xe register-resident ----
        float lu_r[4];
        for (int sit = 0; sit < SINK_ITERS; ++sit) {
            // row sums: lu[i] = 1 / sum_j Xe[i][j]*rv[j]
            ulonglong2 rv0 = *(const ulonglong2*)&rv[j0];
            ulonglong2 rv1 = *(const ulonglong2*)&rv[j0 + 64];
            ull R[4] = { rv0.x, rv0.y, rv1.x, rv1.y };
#pragma unroll
            for (int r = 0; r < 4; ++r) {
                ull s2 = 0ull;
#pragma unroll
                for (int c = 0; c < 4; ++c) ffma2(s2, accC[r*4+c], R[c]);
                F2U u; u.u = s2;
                float s = u.f.x + u.f.y;
#pragma unroll
                for (int off = 1; off < 16; off <<= 1)
                    s += __shfl_xor_sync(0xffffffffu, s, off);
                lu_r[r] = __fdividef(1.0f, s);
            }
            // col partials: cp[j-chunk] = sum_{r in tile} lu[i0+r]*Xe
            ull cp0 = 0, cp1 = 0, cp2 = 0, cp3 = 0;
#pragma unroll
            for (int r = 0; r < 4; ++r) {
                ull L = splat2(lu_r[r]);
                ffma2(cp0, L, accC[r*4+0]);
                ffma2(cp1, L, accC[r*4+1]);
                ffma2(cp2, L, accC[r*4+2]);
                ffma2(cp3, L, accC[r*4+3]);
            }
            { ulonglong2 v; v.x = cp0; v.y = cp1;
              *(ulonglong2*)&psc[ty*S + j0] = v; }
            { ulonglong2 v; v.x = cp2; v.y = cp3;
              *(ulonglong2*)&psc[ty*S + j0 + 64] = v; }
            __syncthreads();
            if (t < 128) {
                float s = 0.0f;
#pragma unroll
                for (int g = 0; g < 32; ++g) s += psc[g*S + t];
                rv[t] = fminf(__fdividef(1.0f, s), 1.0f);
            }
            __syncthreads();
        }

        // ---- X_new = lu * Xe * rv^T ----
        ulonglong2 rv0 = *(const ulonglong2*)&rv[j0];
        ulonglong2 rv1 = *(const ulonglong2*)&rv[j0 + 64];
        ull R[4] = { rv0.x, rv0.y, rv1.x, rv1.y };
        ull P[16];
#pragma unroll
        for (int r = 0; r < 4; ++r) {
            ull L = splat2(lu_r[r]);
#pragma unroll
            for (int c = 0; c < 4; ++c)
                P[r*4+c] = mul2(mul2(L, accC[r*4+c]), R[c]);
        }
        if (it + 1 < GROMOV_ITERS) {
            // store product to W, then transpose W -> XT
#pragma unroll
            for (int r = 0; r < 4; ++r) {
                ulonglong2 s0; s0.x = P[r*4+0]; s0.y = P[r*4+1];
                ulonglong2 s1; s1.x = P[r*4+2]; s1.y = P[r*4+3];
                *(ulonglong2*)&W[(i0+r)*S + j0]      = s0;
                *(ulonglong2*)&W[(i0+r)*S + j0 + 64] = s1;
            }
            __syncthreads();
            int ti = t & 127, tg = t >> 7;
#pragma unroll
            for (int c = 0; c < 8; ++c) {
                float4 v = *(const float4*)&W[ti*S + tg*32 + c*4];
                int jb = tg*32 + c*4;
                XT[(jb+0)*S + ti] = v.x;
                XT[(jb+1)*S + ti] = v.y;
                XT[(jb+2)*S + ti] = v.z;
                XT[(jb+3)*S + ti] = v.w;
            }
            // visibility guaranteed by next phase-A prologue syncs
        } else {
#pragma unroll
            for (int r = 0; r < 4; ++r) {
                ulonglong2 s0; s0.x = P[r*4+0]; s0.y = P[r*4+1];
                ulonglong2 s1; s1.x = P[r*4+2]; s1.y = P[r*4+3];
                *(ulonglong2*)&outb[(i0+r)*N + j0]      = s0;
                *(ulonglong2*)&outb[(i0+r)*N + j0 + 64] = s1;
            }
        }
    }
}

extern "C" void kernel_launch(void* const* d_in, const int* in_sizes, int n_in,
                              void* d_out, int out_size)
{
    const float* X  = (const float*)d_in[0];
    const float* F1 = (const float*)d_in[1];
    const float* F2 = (const float*)d_in[2];
    const float* Kp = (const float*)d_in[3];
    float* out = (float*)d_out;

    int bs = in_sizes[0] / (N * N);

    size_t smem = (size_t)(2*N*S + 2*8*S + 32*S + 128 + 17 + 15) * sizeof(float);
    cudaFuncSetAttribute(gw_kernel, cudaFuncAttributeMaxDynamicSharedMemorySize, (int)smem);
    gw_kernel<<<bs, THREADS, smem>>>(X, F1, F2, Kp, out);
}

// round 6
// speedup vs baseline: 2.1277x; 1.6459x over previous
#include <cuda_runtime.h>
#include <cuda_bf16.h>
#include <cstdint>

#define TAU_F 0.1f
#define GROMOV_ITERS 15
#define SINK_ITERS 15
#define THREADS 512
#define MAXB 2048
#define SB 272              // smem/global tile row stride (bytes), 128 bf16 cols + pad
#define TS 34816            // tile size bytes = 128*272

typedef unsigned long long ull;
typedef uint32_t u32;

// preconverted bf16 hi/lo tiles per batch: F2H, F2L, F1H, F1L (each TS bytes)
__device__ __align__(16) unsigned char g_tiles[(size_t)MAXB * 4 * TS];

// ---------------- helpers ----------------
__device__ __forceinline__ ull splat2(float x) {
    ull r; asm("mov.b64 %0, {%1, %1};" : "=l"(r) : "f"(x)); return r;
}
__device__ __forceinline__ void ffma2(ull &d, ull a, ull b) {
    asm("fma.rn.f32x2 %0, %1, %2, %0;" : "+l"(d) : "l"(a), "l"(b));
}
__device__ __forceinline__ ull mul2(ull a, ull b) {
    ull d; asm("mul.rn.f32x2 %0, %1, %2;" : "=l"(d) : "l"(a), "l"(b)); return d;
}
union F2U { ull u; float2 f; };
union B2U { __nv_bfloat162 b; u32 u; };

__device__ __forceinline__ void split_bf16(float x, __nv_bfloat16 &h, __nv_bfloat16 &l) {
    h = __float2bfloat16_rn(x);
    l = __float2bfloat16_rn(x - __bfloat162float(h));
}
__device__ __forceinline__ u32 packb(__nv_bfloat16 a, __nv_bfloat16 b) {
    B2U u; u.b = __nv_bfloat162(a, b); return u.u;
}

__device__ __forceinline__ u32 smem_u32(const void* p) {
    u32 a; asm("{ .reg .u64 t; cvta.to.shared.u64 t, %1; cvt.u32.u64 %0, t; }" : "=r"(a) : "l"(p));
    return a;
}

__device__ __forceinline__ void ldsm4(u32* r, u32 a) {
    asm volatile("ldmatrix.sync.aligned.m8n8.x4.shared.b16 {%0,%1,%2,%3}, [%4];"
                 : "=r"(r[0]), "=r"(r[1]), "=r"(r[2]), "=r"(r[3]) : "r"(a));
}
__device__ __forceinline__ void ldsm4t(u32* r, u32 a) {
    asm volatile("ldmatrix.sync.aligned.m8n8.x4.trans.shared.b16 {%0,%1,%2,%3}, [%4];"
                 : "=r"(r[0]), "=r"(r[1]), "=r"(r[2]), "=r"(r[3]) : "r"(a));
}
__device__ __forceinline__ void hmma(float* d, u32 a0, u32 a1, u32 a2, u32 a3,
                                     u32 b0, u32 b1) {
    asm volatile("mma.sync.aligned.m16n8k16.row.col.f32.bf16.bf16.f32 "
                 "{%0,%1,%2,%3}, {%4,%5,%6,%7}, {%8,%9}, {%0,%1,%2,%3};"
                 : "+f"(d[0]), "+f"(d[1]), "+f"(d[2]), "+f"(d[3])
                 : "r"(a0), "r"(a1), "r"(a2), "r"(a3), "r"(b0), "r"(b1));
}
// 8 mma: both m-tiles (a8[0..3], a8[4..7]) x 2 n-tiles (b[0,1], b[2,3]) into acc njj0, njj0+1
__device__ __forceinline__ void mma_blk(float* acc, int njj0, const u32* a8, const u32* b) {
    hmma(acc + (njj0)     * 4, a8[0], a8[1], a8[2], a8[3], b[0], b[1]);
    hmma(acc + (njj0 + 1) * 4, a8[0], a8[1], a8[2], a8[3], b[2], b[3]);
    hmma(acc + (4 + njj0)     * 4, a8[4], a8[5], a8[6], a8[7], b[0], b[1]);
    hmma(acc + (4 + njj0 + 1) * 4, a8[4], a8[5], a8[6], a8[7], b[2], b[3]);
}

#define CP_COMMIT() asm volatile("cp.async.commit_group;" ::: "memory")
#define CP_WAIT0()  asm volatile("cp.async.wait_group 0;" ::: "memory")
__device__ __forceinline__ void cp16(u32 saddr, const void* g) {
    asm volatile("cp.async.cg.shared.global [%0], [%1], 16;" :: "r"(saddr), "l"(g) : "memory");
}

// ---------------- smem layout (byte offsets) ----------------
#define O_XH   0
#define O_XL   (TS)
#define O_F2H  (2*TS)       // Z overwrites here after G12; cp.async refills post-G34
#define O_F2L  (3*TS)
#define O_F1H  (4*TS)
#define O_F1L  (5*TS)
#define O_PSR  (6*TS)            // psrow[4][128] float
#define O_PSC  (O_PSR + 2048)    // pscol[4][128] float
#define O_RED  (O_PSC + 2048)    // red[17] float
#define SM_TOT (O_RED + 128)

// ===================== prep: split F1/F2 to bf16 hi/lo padded tiles =====================
__global__ __launch_bounds__(THREADS, 1)
void prep_kernel(const float* __restrict__ F1g, const float* __restrict__ F2g)
{
    const int t = threadIdx.x, b = blockIdx.x;
    const int row = t >> 2, cb = (t & 3) * 32;
    unsigned char* ob = g_tiles + (size_t)b * 4 * TS;
#pragma unroll
    for (int m = 0; m < 2; ++m) {
        const float* src = (m ? F1g : F2g) + (size_t)b * 16384;
        unsigned char* dH = ob + (size_t)(m ? 2 : 0) * TS + row * SB;
        unsigned char* dL = dH + TS;
#pragma unroll
        for (int q = 0; q < 8; ++q) {
            float4 v = *(const float4*)(src + row * 128 + cb + 4 * q);
            __nv_bfloat16 h0, l0, h1, l1, h2, l2, h3, l3;
            split_bf16(v.x, h0, l0); split_bf16(v.y, h1, l1);
            split_bf16(v.z, h2, l2); split_bf16(v.w, h3, l3);
            *(uint2*)(dH + (cb + 4 * q) * 2) = make_uint2(packb(h0, h1), packb(h2, h3));
            *(uint2*)(dL + (cb + 4 * q) * 2) = make_uint2(packb(l0, l1), packb(l2, l3));
        }
    }
}

// ===================== main kernel =====================
__global__ __launch_bounds__(THREADS, 1)
void gw_kernel(const float* __restrict__ Xg, const float* __restrict__ Kpg,
               float* __restrict__ outg)
{
    extern __shared__ __align__(128) unsigned char sb[];
    const u32 sbu = smem_u32(sb);
    float* psrow = (float*)(sb + O_PSR);
    float* pscol = (float*)(sb + O_PSC);
    float* red   = (float*)(sb + O_RED);

    const int t = threadIdx.x;
    const int w = t >> 5, lane = t & 31;
    const int g = lane >> 2, t4 = lane & 3;
    const int m0 = (w & 3) * 32, n0 = (w >> 2) * 32;
    const int b = blockIdx.x;

    const float* Xb = Xg  + (size_t)b * 16384;
    const float* Kp = Kpg + (size_t)b * 16384;
    float* outb     = outg + (size_t)b * 16384;
    const unsigned char* gb = g_tiles + (size_t)b * 4 * TS;

    // ldmatrix lane-pattern offsets (bytes)
    const int l = lane;
    const u32 pA  = (u32)((l & 15) * SB + ((l >> 4) << 3) * 2);
    const u32 pAT = (u32)(((l & 7) + ((l >> 4) << 3)) * SB + ((l >> 3) & 1) * 16);
    const u32 pBt = (u32)(((l & 7) + (((l >> 3) & 1) << 3)) * SB + ((l >> 4) << 3) * 2);
    const u32 pBn = (u32)(((l & 7) + ((l >> 4) << 3)) * SB + (((l >> 3) & 1) << 3) * 2);

    // warp base addresses
    const u32 aXH  = sbu + O_XH  + m0 * SB + pA;
    const u32 aXL  = sbu + O_XL  + m0 * SB + pA;
    const u32 aF1H = sbu + O_F1H + m0 * SB + pA;
    const u32 aF1L = sbu + O_F1L + m0 * SB + pA;
    const u32 atF1H = sbu + O_F1H + m0 * 2 + pAT;
    const u32 atF1L = sbu + O_F1L + m0 * 2 + pAT;
    const u32 btXH = sbu + O_XH  + n0 * 2 + pBt;   // Y after overwrite
    const u32 btXL = sbu + O_XL  + n0 * 2 + pBt;
    const u32 btF2H = sbu + O_F2H + n0 * 2 + pBt;  // F2 (G12) / Z (G34)
    const u32 btF2L = sbu + O_F2L + n0 * 2 + pBt;
    const u32 bnF2H = sbu + O_F2H + n0 * SB + pBn;
    const u32 bnF2L = sbu + O_F2L + n0 * SB + pBn;

    // ---- prologue: X -> bf16 hi/lo tile; prefetch F2/F1 tiles ----
    {
        const int row = t >> 2, cb = (t & 3) * 32;
        unsigned char* dH = sb + O_XH + row * SB;
        unsigned char* dL = sb + O_XL + row * SB;
#pragma unroll
        for (int q = 0; q < 8; ++q) {
            float4 v = *(const float4*)(Xb + row * 128 + cb + 4 * q);
            __nv_bfloat16 h0, l0, h1, l1, h2, l2, h3, l3;
            split_bf16(v.x, h0, l0); split_bf16(v.y, h1, l1);
            split_bf16(v.z, h2, l2); split_bf16(v.w, h3, l3);
            *(uint2*)(dH + (cb + 4 * q) * 2) = make_uint2(packb(h0, h1), packb(h2, h3));
            *(uint2*)(dL + (cb + 4 * q) * 2) = make_uint2(packb(l0, l1), packb(l2, l3));
        }
    }
    for (int i = t; i < 4 * TS / 16; i += THREADS)
        cp16(sbu + O_F2H + i * 16, gb + i * 16);
    CP_COMMIT();

    float accY[32], accZ[32], acc[32];
    ull xe2[16], rv2[4];
    float lu4[4];

    for (int it = 0; it < GROMOV_ITERS; ++it) {
        CP_WAIT0();
        __syncthreads();

        // ================= G12: Y = X*F2, Z = X*F2^T =================
#pragma unroll
        for (int q = 0; q < 32; ++q) { accY[q] = 0.0f; accZ[q] = 0.0f; }
#pragma unroll 1
        for (int kk = 0; kk < 8; ++kk) {
            const u32 kb = kk * 32, krb = kk * 16 * SB;
            u32 ah[8], al[8], bq[4];
            ldsm4(ah,     aXH + kb); ldsm4(ah + 4, aXH + 16 * SB + kb);
            ldsm4(al,     aXL + kb); ldsm4(al + 4, aXL + 16 * SB + kb);
#pragma unroll
            for (int h2 = 0; h2 < 2; ++h2) {
                ldsm4t(bq, btF2H + krb + h2 * 32);
                mma_blk(accY, 2 * h2, ah, bq); mma_blk(accY, 2 * h2, al, bq);
                ldsm4t(bq, btF2L + krb + h2 * 32);
                mma_blk(accY, 2 * h2, ah, bq); mma_blk(accY, 2 * h2, al, bq);
                ldsm4(bq, bnF2H + h2 * 16 * SB + kb);
                mma_blk(accZ, 2 * h2, ah, bq); mma_blk(accZ, 2 * h2, al, bq);
                ldsm4(bq, bnF2L + h2 * 16 * SB + kb);
                mma_blk(accZ, 2 * h2, ah, bq); mma_blk(accZ, 2 * h2, al, bq);
            }
        }
        __syncthreads();
        // store Y -> X slots, Z -> F2 slots (bf16 hi/lo)
#pragma unroll
        for (int mi = 0; mi < 2; ++mi)
#pragma unroll
            for (int njj = 0; njj < 4; ++njj) {
                const float* y = accY + (mi * 4 + njj) * 4;
                const float* z = accZ + (mi * 4 + njj) * 4;
                const int c0 = n0 + 8 * njj + 2 * t4;
#pragma unroll
                for (int rh = 0; rh < 2; ++rh) {
                    const int r = m0 + 16 * mi + 8 * rh + g;
                    __nv_bfloat16 h0, l0, h1, l1;
                    split_bf16(y[2 * rh],     h0, l0);
                    split_bf16(y[2 * rh + 1], h1, l1);
                    *(u32*)(sb + O_XH + r * SB + c0 * 2) = packb(h0, h1);
                    *(u32*)(sb + O_XL + r * SB + c0 * 2) = packb(l0, l1);
                    split_bf16(z[2 * rh],     h0, l0);
                    split_bf16(z[2 * rh + 1], h1, l1);
                    *(u32*)(sb + O_F2H + r * SB + c0 * 2) = packb(h0, h1);
                    *(u32*)(sb + O_F2L + r * SB + c0 * 2) = packb(l0, l1);
                }
            }
        __syncthreads();

        // ================= G34: C = Kp + F1*Y + F1^T*Z =================
#pragma unroll
        for (int mi = 0; mi < 2; ++mi)
#pragma unroll
            for (int njj = 0; njj < 4; ++njj) {
                float* d = acc + (mi * 4 + njj) * 4;
                const int c0 = n0 + 8 * njj + 2 * t4;
                float2 kA = *(const float2*)(Kp + (m0 + 16 * mi + g) * 128 + c0);
                float2 kB = *(const float2*)(Kp + (m0 + 16 * mi + 8 + g) * 128 + c0);
                d[0] = kA.x; d[1] = kA.y; d[2] = kB.x; d[3] = kB.y;
            }
#pragma unroll 1
        for (int kk = 0; kk < 8; ++kk) {
            const u32 kb = kk * 32, krb = kk * 16 * SB;
            u32 ah[8], al[8], bq[4];
            // C += F1 * Y
            ldsm4(ah,     aF1H + kb); ldsm4(ah + 4, aF1H + 16 * SB + kb);
            ldsm4(al,     aF1L + kb); ldsm4(al + 4, aF1L + 16 * SB + kb);
#pragma unroll
            for (int h2 = 0; h2 < 2; ++h2) {
                ldsm4t(bq, btXH + krb + h2 * 32);
                mma_blk(acc, 2 * h2, ah, bq); mma_blk(acc, 2 * h2, al, bq);
                ldsm4t(bq, btXL + krb + h2 * 32);
                mma_blk(acc, 2 * h2, ah, bq); mma_blk(acc, 2 * h2, al, bq);
            }
            // C += F1^T * Z
            ldsm4t(ah,     atF1H + krb); ldsm4t(ah + 4, atF1H + krb + 32);
            ldsm4t(al,     atF1L + krb); ldsm4t(al + 4, atF1L + krb + 32);
#pragma unroll
            for (int h2 = 0; h2 < 2; ++h2) {
                ldsm4t(bq, btF2H + krb + h2 * 32);
                mma_blk(acc, 2 * h2, ah, bq); mma_blk(acc, 2 * h2, al, bq);
                ldsm4t(bq, btF2L + krb + h2 * 32);
                mma_blk(acc, 2 * h2, ah, bq); mma_blk(acc, 2 * h2, al, bq);
            }
        }
        __syncthreads();

        // prefetch next iter's F2/F1 (overwrites Z + F1 slots; all disjoint from epilogue)
        if (it + 1 < GROMOV_ITERS) {
            for (int i = t; i < 4 * TS / 16; i += THREADS)
                cp16(sbu + O_F2H + i * 16, gb + i * 16);
            CP_COMMIT();
        }

        // ---- L-inf norm ----
        float mx = 0.0f;
#pragma unroll
        for (int q = 0; q < 32; ++q) mx = fmaxf(mx, fabsf(acc[q]));
#pragma unroll
        for (int off = 16; off > 0; off >>= 1)
            mx = fmaxf(mx, __shfl_xor_sync(0xffffffffu, mx, off));
        if (lane == 0) red[w] = mx;
        __syncthreads();
        if (t == 0) {
            float n = red[0];
#pragma unroll
            for (int q = 1; q < 16; ++q) n = fmaxf(n, red[q]);
            red[16] = __fdividef(1.0f, n * TAU_F);
        }
        __syncthreads();
        const float scale = red[16];

        // ---- Xe = exp(C*scale) in registers; frag layout [mi][rh][njj] pairs ----
#pragma unroll
        for (int mi = 0; mi < 2; ++mi)
#pragma unroll
            for (int rh = 0; rh < 2; ++rh)
#pragma unroll
                for (int njj = 0; njj < 4; ++njj) {
                    const float* d = acc + (mi * 4 + njj) * 4 + 2 * rh;
                    F2U u;
                    u.f.x = __expf(d[0] * scale);
                    u.f.y = __expf(d[1] * scale);
                    xe2[(mi * 2 + rh) * 4 + njj] = u.u;
                }
#pragma unroll
        for (int njj = 0; njj < 4; ++njj) rv2[njj] = splat2(1.0f);

        // ---- Sinkhorn ----
        for (int sit = 0; sit < SINK_ITERS; ++sit) {
#pragma unroll
            for (int mr = 0; mr < 4; ++mr) {       // mr = mi*2+rh
                ull s2 = 0ull;
#pragma unroll
                for (int njj = 0; njj < 4; ++njj) ffma2(s2, xe2[mr * 4 + njj], rv2[njj]);
                F2U u; u.u = s2;
                float s = u.f.x + u.f.y;
                s += __shfl_xor_sync(0xffffffffu, s, 1);
                s += __shfl_xor_sync(0xffffffffu, s, 2);
                if (t4 == 0) {
                    const int r = m0 + 16 * (mr >> 1) + 8 * (mr & 1) + g;
                    psrow[(w >> 2) * 128 + r] = s;
                }
            }
            __syncthreads();
#pragma unroll
            for (int mr = 0; mr < 4; ++mr) {
                const int r = m0 + 16 * (mr >> 1) + 8 * (mr & 1) + g;
                lu4[mr] = __fdividef(1.0f,
                    psrow[r] + psrow[128 + r] + psrow[256 + r] + psrow[384 + r]);
            }
#pragma unroll
            for (int njj = 0; njj < 4; ++njj) {
                ull cs = 0ull;
#pragma unroll
                for (int mr = 0; mr < 4; ++mr) ffma2(cs, xe2[mr * 4 + njj], splat2(lu4[mr]));
                F2U u; u.u = cs;
                u.f.x += __shfl_xor_sync(0xffffffffu, u.f.x, 4);
                u.f.y += __shfl_xor_sync(0xffffffffu, u.f.y, 4);
                u.f.x += __shfl_xor_sync(0xffffffffu, u.f.x, 8);
                u.f.y += __shfl_xor_sync(0xffffffffu, u.f.y, 8);
                u.f.x += __shfl_xor_sync(0xffffffffu, u.f.x, 16);
                u.f.y += __shfl_xor_sync(0xffffffffu, u.f.y, 16);
                if (lane < 4)
                    *(float2*)&pscol[(w & 3) * 128 + n0 + 8 * njj + 2 * t4] = u.f;
            }
            __syncthreads();
#pragma unroll
            for (int njj = 0; njj < 4; ++njj) {
                const int c0 = n0 + 8 * njj + 2 * t4;
                float2 a0 = *(const float2*)&pscol[c0];
                float2 a1 = *(const float2*)&pscol[128 + c0];
                float2 a2 = *(const float2*)&pscol[256 + c0];
                float2 a3 = *(const float2*)&pscol[384 + c0];
                F2U u;
                u.f.x = fminf(__fdividef(1.0f, a0.x + a1.x + a2.x + a3.x), 1.0f);
                u.f.y = fminf(__fdividef(1.0f, a0.y + a1.y + a2.y + a3.y), 1.0f);
                rv2[njj] = u.u;
            }
            __syncthreads();
        }

        // ---- X_new = lu * Xe * rv^T ----
        if (it + 1 < GROMOV_ITERS) {
#pragma unroll
            for (int mr = 0; mr < 4; ++mr) {
                const int r = m0 + 16 * (mr >> 1) + 8 * (mr & 1) + g;
                const ull L = splat2(lu4[mr]);
#pragma unroll
                for (int njj = 0; njj < 4; ++njj) {
                    const int c0 = n0 + 8 * njj + 2 * t4;
                    F2U u; u.u = mul2(mul2(L, xe2[mr * 4 + njj]), rv2[njj]);
                    __nv_bfloat16 h0, l0, h1, l1;
                    split_bf16(u.f.x, h0, l0); split_bf16(u.f.y, h1, l1);
                    *(u32*)(sb + O_XH + r * SB + c0 * 2) = packb(h0, h1);
                    *(u32*)(sb + O_XL + r * SB + c0 * 2) = packb(l0, l1);
                }
            }
        } else {
#pragma unroll
            for (int mr = 0; mr < 4; ++mr) {
                const int r = m0 + 16 * (mr >> 1) + 8 * (mr & 1) + g;
                const ull L = splat2(lu4[mr]);
#pragma unroll
                for (int njj = 0; njj < 4; ++njj) {
                    const int c0 = n0 + 8 * njj + 2 * t4;
                    F2U u; u.u = mul2(mul2(L, xe2[mr * 4 + njj]), rv2[njj]);
                    *(float2*)(outb + r * 128 + c0) = u.f;
                }
            }
        }
    }
}

extern "C" void kernel_launch(void* const* d_in, const int* in_sizes, int n_in,
                              void* d_out, int out_size)
{
    const float* X  = (const float*)d_in[0];
    const float* F1 = (const float*)d_in[1];
    const float* F2 = (const float*)d_in[2];
    const float* Kp = (const float*)d_in[3];
    float* out = (float*)d_out;

    int bs = in_sizes[0] / (128 * 128);
    if (bs > MAXB) bs = MAXB;

    prep_kernel<<<bs, THREADS>>>(F1, F2);

    cudaFuncSetAttribute(gw_kernel, cudaFuncAttributeMaxDynamicSharedMemorySize, SM_TOT);
    gw_kernel<<<bs, THREADS, SM_TOT>>>(X, Kp, out);
}

// round 7
// speedup vs baseline: 2.4143x; 1.1347x over previous
#include <cuda_runtime.h>
#include <cuda_bf16.h>
#include <cstdint>

#define TAU_F 0.1f
#define GROMOV_ITERS 15
#define SINK_ITERS 15
#define THREADS 512
#define MAXB 2048
#define SB 272              // smem/global tile row stride (bytes), 128 bf16 cols + pad
#define TS 34816            // tile size bytes = 128*272

typedef unsigned long long ull;
typedef uint32_t u32;

// preconverted bf16 hi/lo tiles per batch: F2H, F2L, F1H, F1L (each TS bytes)
__device__ __align__(16) unsigned char g_tiles[(size_t)MAXB * 4 * TS];

// ---------------- helpers ----------------
__device__ __forceinline__ ull splat2(float x) {
    ull r; asm("mov.b64 %0, {%1, %1};" : "=l"(r) : "f"(x)); return r;
}
__device__ __forceinline__ void ffma2(ull &d, ull a, ull b) {
    asm("fma.rn.f32x2 %0, %1, %2, %0;" : "+l"(d) : "l"(a), "l"(b));
}
__device__ __forceinline__ ull mul2(ull a, ull b) {
    ull d; asm("mul.rn.f32x2 %0, %1, %2;" : "=l"(d) : "l"(a), "l"(b)); return d;
}
union F2U { ull u; float2 f; };
union B2U { __nv_bfloat162 b; u32 u; };

__device__ __forceinline__ void split_bf16(float x, __nv_bfloat16 &h, __nv_bfloat16 &l) {
    h = __float2bfloat16_rn(x);
    l = __float2bfloat16_rn(x - __bfloat162float(h));
}
__device__ __forceinline__ u32 packb(__nv_bfloat16 a, __nv_bfloat16 b) {
    B2U u; u.b = __nv_bfloat162(a, b); return u.u;
}

__device__ __forceinline__ u32 smem_u32(const void* p) {
    u32 a; asm("{ .reg .u64 t; cvta.to.shared.u64 t, %1; cvt.u32.u64 %0, t; }" : "=r"(a) : "l"(p));
    return a;
}

__device__ __forceinline__ void ldsm4(u32* r, u32 a) {
    asm volatile("ldmatrix.sync.aligned.m8n8.x4.shared.b16 {%0,%1,%2,%3}, [%4];"
                 : "=r"(r[0]), "=r"(r[1]), "=r"(r[2]), "=r"(r[3]) : "r"(a));
}
__device__ __forceinline__ void ldsm4t(u32* r, u32 a) {
    asm volatile("ldmatrix.sync.aligned.m8n8.x4.trans.shared.b16 {%0,%1,%2,%3}, [%4];"
                 : "=r"(r[0]), "=r"(r[1]), "=r"(r[2]), "=r"(r[3]) : "r"(a));
}
__device__ __forceinline__ void hmma(float* d, u32 a0, u32 a1, u32 a2, u32 a3,
                                     u32 b0, u32 b1) {
    asm volatile("mma.sync.aligned.m16n8k16.row.col.f32.bf16.bf16.f32 "
                 "{%0,%1,%2,%3}, {%4,%5,%6,%7}, {%8,%9}, {%0,%1,%2,%3};"
                 : "+f"(d[0]), "+f"(d[1]), "+f"(d[2]), "+f"(d[3])
                 : "r"(a0), "r"(a1), "r"(a2), "r"(a3), "r"(b0), "r"(b1));
}
// 8 mma: both m-tiles (a8[0..3], a8[4..7]) x 2 n-tiles (b[0,1], b[2,3]) into acc njj0, njj0+1
__device__ __forceinline__ void mma_blk(float* acc, int njj0, const u32* a8, const u32* b) {
    hmma(acc + (njj0)     * 4, a8[0], a8[1], a8[2], a8[3], b[0], b[1]);
    hmma(acc + (njj0 + 1) * 4, a8[0], a8[1], a8[2], a8[3], b[2], b[3]);
    hmma(acc + (4 + njj0)     * 4, a8[4], a8[5], a8[6], a8[7], b[0], b[1]);
    hmma(acc + (4 + njj0 + 1) * 4, a8[4], a8[5], a8[6], a8[7], b[2], b[3]);
}

#define CP_COMMIT() asm volatile("cp.async.commit_group;" ::: "memory")
#define CP_WAIT0()  asm volatile("cp.async.wait_group 0;" ::: "memory")
__device__ __forceinline__ void cp16(u32 saddr, const void* g) {
    asm volatile("cp.async.cg.shared.global [%0], [%1], 16;" :: "r"(saddr), "l"(g) : "memory");
}

// ---------------- smem layout (byte offsets) ----------------
#define O_XH   0
#define O_XL   (TS)
#define O_F2H  (2*TS)       // Z overwrites here after G12; cp.async refills post-G34
#define O_F2L  (3*TS)
#define O_F1H  (4*TS)
#define O_F1L  (5*TS)
#define O_PSR  (6*TS)            // psrow[4][128] float
#define O_PSC  (O_PSR + 2048)    // pscol[4][128] float
#define O_RED  (O_PSC + 2048)    // red[17] float
#define SM_TOT (O_RED + 128)

// ===================== prep: split F1/F2 to bf16 hi/lo padded tiles =====================
__global__ __launch_bounds__(THREADS, 1)
void prep_kernel(const float* __restrict__ F1g, const float* __restrict__ F2g)
{
    const int t = threadIdx.x, b = blockIdx.x;
    const int row = t >> 2, cb = (t & 3) * 32;
    unsigned char* ob = g_tiles + (size_t)b * 4 * TS;
#pragma unroll
    for (int m = 0; m < 2; ++m) {
        const float* src = (m ? F1g : F2g) + (size_t)b * 16384;
        unsigned char* dH = ob + (size_t)(m ? 2 : 0) * TS + row * SB;
        unsigned char* dL = dH + TS;
#pragma unroll
        for (int q = 0; q < 8; ++q) {
            float4 v = *(const float4*)(src + row * 128 + cb + 4 * q);
            __nv_bfloat16 h0, l0, h1, l1, h2, l2, h3, l3;
            split_bf16(v.x, h0, l0); split_bf16(v.y, h1, l1);
            split_bf16(v.z, h2, l2); split_bf16(v.w, h3, l3);
            *(uint2*)(dH + (cb + 4 * q) * 2) = make_uint2(packb(h0, h1), packb(h2, h3));
            *(uint2*)(dL + (cb + 4 * q) * 2) = make_uint2(packb(l0, l1), packb(l2, l3));
        }
    }
}

// ===================== main kernel =====================
__global__ __launch_bounds__(THREADS, 1)
void gw_kernel(const float* __restrict__ Xg, const float* __restrict__ Kpg,
               float* __restrict__ outg)
{
    extern __shared__ __align__(128) unsigned char sb[];
    const u32 sbu = smem_u32(sb);
    float* psrow = (float*)(sb + O_PSR);
    float* pscol = (float*)(sb + O_PSC);
    float* red   = (float*)(sb + O_RED);

    const int t = threadIdx.x;
    const int w = t >> 5, lane = t & 31;
    const int g = lane >> 2, t4 = lane & 3;
    const int m0 = (w & 3) * 32, n0 = (w >> 2) * 32;
    const int b = blockIdx.x;

    const float* Xb = Xg  + (size_t)b * 16384;
    const float* Kp = Kpg + (size_t)b * 16384;
    float* outb     = outg + (size_t)b * 16384;
    const unsigned char* gb = g_tiles + (size_t)b * 4 * TS;

    // ldmatrix lane-pattern offsets (bytes)
    const int l = lane;
    const u32 pA  = (u32)((l & 15) * SB + ((l >> 4) << 3) * 2);
    const u32 pAT = (u32)(((l & 7) + ((l >> 4) << 3)) * SB + ((l >> 3) & 1) * 16);
    const u32 pBt = (u32)(((l & 7) + (((l >> 3) & 1) << 3)) * SB + ((l >> 4) << 3) * 2);
    const u32 pBn = (u32)(((l & 7) + ((l >> 4) << 3)) * SB + (((l >> 3) & 1) << 3) * 2);

    // warp base addresses
    const u32 aXH  = sbu + O_XH  + m0 * SB + pA;
    const u32 aXL  = sbu + O_XL  + m0 * SB + pA;
    const u32 aF1H = sbu + O_F1H + m0 * SB + pA;
    const u32 aF1L = sbu + O_F1L + m0 * SB + pA;
    const u32 atF1H = sbu + O_F1H + m0 * 2 + pAT;
    const u32 atF1L = sbu + O_F1L + m0 * 2 + pAT;
    const u32 btXH = sbu + O_XH  + n0 * 2 + pBt;   // Y after overwrite
    const u32 btXL = sbu + O_XL  + n0 * 2 + pBt;
    const u32 btF2H = sbu + O_F2H + n0 * 2 + pBt;  // F2 (G12) / Z (G34)
    const u32 btF2L = sbu + O_F2L + n0 * 2 + pBt;
    const u32 bnF2H = sbu + O_F2H + n0 * SB + pBn;
    const u32 bnF2L = sbu + O_F2L + n0 * SB + pBn;

    // ---- prologue: X -> bf16 hi/lo tile; prefetch F2/F1 tiles ----
    {
        const int row = t >> 2, cb = (t & 3) * 32;
        unsigned char* dH = sb + O_XH + row * SB;
        unsigned char* dL = sb + O_XL + row * SB;
#pragma unroll
        for (int q = 0; q < 8; ++q) {
            float4 v = *(const float4*)(Xb + row * 128 + cb + 4 * q);
            __nv_bfloat16 h0, l0, h1, l1, h2, l2, h3, l3;
            split_bf16(v.x, h0, l0); split_bf16(v.y, h1, l1);
            split_bf16(v.z, h2, l2); split_bf16(v.w, h3, l3);
            *(uint2*)(dH + (cb + 4 * q) * 2) = make_uint2(packb(h0, h1), packb(h2, h3));
            *(uint2*)(dL + (cb + 4 * q) * 2) = make_uint2(packb(l0, l1), packb(l2, l3));
        }
    }
    for (int i = t; i < 4 * TS / 16; i += THREADS)
        cp16(sbu + O_F2H + i * 16, gb + i * 16);
    CP_COMMIT();

    float accY[32], accZ[32], acc[32];
    ull xe2[16], rv2[4];
    float lu4[4];

    for (int it = 0; it < GROMOV_ITERS; ++it) {
        CP_WAIT0();
        __syncthreads();

        // ====== G12: Y = X*F2, Z = X*F2^T  (3-term split: hh + lh + hl) ======
#pragma unroll
        for (int q = 0; q < 32; ++q) { accY[q] = 0.0f; accZ[q] = 0.0f; }
#pragma unroll 1
        for (int kk = 0; kk < 8; ++kk) {
            const u32 kb = kk * 32, krb = kk * 16 * SB;
            u32 ah[8], al[8], bq[4];
            ldsm4(ah,     aXH + kb); ldsm4(ah + 4, aXH + 16 * SB + kb);
            ldsm4(al,     aXL + kb); ldsm4(al + 4, aXL + 16 * SB + kb);
#pragma unroll
            for (int h2 = 0; h2 < 2; ++h2) {
                ldsm4t(bq, btF2H + krb + h2 * 32);
                mma_blk(accY, 2 * h2, ah, bq); mma_blk(accY, 2 * h2, al, bq);
                ldsm4t(bq, btF2L + krb + h2 * 32);
                mma_blk(accY, 2 * h2, ah, bq);
                ldsm4(bq, bnF2H + h2 * 16 * SB + kb);
                mma_blk(accZ, 2 * h2, ah, bq); mma_blk(accZ, 2 * h2, al, bq);
                ldsm4(bq, bnF2L + h2 * 16 * SB + kb);
                mma_blk(accZ, 2 * h2, ah, bq);
            }
        }
        __syncthreads();
        // store Y -> X slots, Z -> F2 slots (bf16 hi/lo)
#pragma unroll
        for (int mi = 0; mi < 2; ++mi)
#pragma unroll
            for (int njj = 0; njj < 4; ++njj) {
                const float* y = accY + (mi * 4 + njj) * 4;
                const float* z = accZ + (mi * 4 + njj) * 4;
                const int c0 = n0 + 8 * njj + 2 * t4;
#pragma unroll
                for (int rh = 0; rh < 2; ++rh) {
                    const int r = m0 + 16 * mi + 8 * rh + g;
                    __nv_bfloat16 h0, l0, h1, l1;
                    split_bf16(y[2 * rh],     h0, l0);
                    split_bf16(y[2 * rh + 1], h1, l1);
                    *(u32*)(sb + O_XH + r * SB + c0 * 2) = packb(h0, h1);
                    *(u32*)(sb + O_XL + r * SB + c0 * 2) = packb(l0, l1);
                    split_bf16(z[2 * rh],     h0, l0);
                    split_bf16(z[2 * rh + 1], h1, l1);
                    *(u32*)(sb + O_F2H + r * SB + c0 * 2) = packb(h0, h1);
                    *(u32*)(sb + O_F2L + r * SB + c0 * 2) = packb(l0, l1);
                }
            }
        __syncthreads();

        // ====== G34: C = Kp + F1*Y + F1^T*Z  (3-term split) ======
#pragma unroll
        for (int mi = 0; mi < 2; ++mi)
#pragma unroll
            for (int njj = 0; njj < 4; ++njj) {
                float* d = acc + (mi * 4 + njj) * 4;
                const int c0 = n0 + 8 * njj + 2 * t4;
                float2 kA = *(const float2*)(Kp + (m0 + 16 * mi + g) * 128 + c0);
                float2 kB = *(const float2*)(Kp + (m0 + 16 * mi + 8 + g) * 128 + c0);
                d[0] = kA.x; d[1] = kA.y; d[2] = kB.x; d[3] = kB.y;
            }
#pragma unroll 1
        for (int kk = 0; kk < 8; ++kk) {
            const u32 kb = kk * 32, krb = kk * 16 * SB;
            u32 ah[8], al[8], bq[4];
            // C += F1 * Y
            ldsm4(ah,     aF1H + kb); ldsm4(ah + 4, aF1H + 16 * SB + kb);
            ldsm4(al,     aF1L + kb); ldsm4(al + 4, aF1L + 16 * SB + kb);
#pragma unroll
            for (int h2 = 0; h2 < 2; ++h2) {
                ldsm4t(bq, btXH + krb + h2 * 32);
                mma_blk(acc, 2 * h2, ah, bq); mma_blk(acc, 2 * h2, al, bq);
                ldsm4t(bq, btXL + krb + h2 * 32);
                mma_blk(acc, 2 * h2, ah, bq);
            }
            // C += F1^T * Z
            ldsm4t(ah,     atF1H + krb); ldsm4t(ah + 4, atF1H + krb + 32);
            ldsm4t(al,     atF1L + krb); ldsm4t(al + 4, atF1L + krb + 32);
#pragma unroll
            for (int h2 = 0; h2 < 2; ++h2) {
                ldsm4t(bq, btF2H + krb + h2 * 32);
                mma_blk(acc, 2 * h2, ah, bq); mma_blk(acc, 2 * h2, al, bq);
                ldsm4t(bq, btF2L + krb + h2 * 32);
                mma_blk(acc, 2 * h2, ah, bq);
            }
        }
        __syncthreads();

        // prefetch next iter's F2/F1 (overwrites Z + F1 slots; all disjoint from epilogue)
        if (it + 1 < GROMOV_ITERS) {
            for (int i = t; i < 4 * TS / 16; i += THREADS)
                cp16(sbu + O_F2H + i * 16, gb + i * 16);
            CP_COMMIT();
        }

        // ---- L-inf norm ----
        float mx = 0.0f;
#pragma unroll
        for (int q = 0; q < 32; ++q) mx = fmaxf(mx, fabsf(acc[q]));
#pragma unroll
        for (int off = 16; off > 0; off >>= 1)
            mx = fmaxf(mx, __shfl_xor_sync(0xffffffffu, mx, off));
        if (lane == 0) red[w] = mx;
        __syncthreads();
        if (t == 0) {
            float n = red[0];
#pragma unroll
            for (int q = 1; q < 16; ++q) n = fmaxf(n, red[q]);
            red[16] = __fdividef(1.0f, n * TAU_F);
        }
        __syncthreads();
        const float scale = red[16];

        // ---- Xe = exp(C*scale) in registers; frag layout [mi][rh][njj] pairs ----
#pragma unroll
        for (int mi = 0; mi < 2; ++mi)
#pragma unroll
            for (int rh = 0; rh < 2; ++rh)
#pragma unroll
                for (int njj = 0; njj < 4; ++njj) {
                    const float* d = acc + (mi * 4 + njj) * 4 + 2 * rh;
                    F2U u;
                    u.f.x = __expf(d[0] * scale);
                    u.f.y = __expf(d[1] * scale);
                    xe2[(mi * 2 + rh) * 4 + njj] = u.u;
                }
#pragma unroll
        for (int njj = 0; njj < 4; ++njj) rv2[njj] = splat2(1.0f);

        // ---- Sinkhorn (2 barriers per inner iter) ----
        for (int sit = 0; sit < SINK_ITERS; ++sit) {
#pragma unroll
            for (int mr = 0; mr < 4; ++mr) {       // mr = mi*2+rh
                ull s2 = 0ull;
#pragma unroll
                for (int njj = 0; njj < 4; ++njj) ffma2(s2, xe2[mr * 4 + njj], rv2[njj]);
                F2U u; u.u = s2;
                float s = u.f.x + u.f.y;
                s += __shfl_xor_sync(0xffffffffu, s, 1);
                s += __shfl_xor_sync(0xffffffffu, s, 2);
                if (t4 == 0) {
                    const int r = m0 + 16 * (mr >> 1) + 8 * (mr & 1) + g;
                    psrow[(w >> 2) * 128 + r] = s;
                }
            }
            __syncthreads();
#pragma unroll
            for (int mr = 0; mr < 4; ++mr) {
                const int r = m0 + 16 * (mr >> 1) + 8 * (mr & 1) + g;
                lu4[mr] = __fdividef(1.0f,
                    psrow[r] + psrow[128 + r] + psrow[256 + r] + psrow[384 + r]);
            }
#pragma unroll
            for (int njj = 0; njj < 4; ++njj) {
                ull cs = 0ull;
#pragma unroll
                for (int mr = 0; mr < 4; ++mr) ffma2(cs, xe2[mr * 4 + njj], splat2(lu4[mr]));
                F2U u; u.u = cs;
                u.f.x += __shfl_xor_sync(0xffffffffu, u.f.x, 4);
                u.f.y += __shfl_xor_sync(0xffffffffu, u.f.y, 4);
                u.f.x += __shfl_xor_sync(0xffffffffu, u.f.x, 8);
                u.f.y += __shfl_xor_sync(0xffffffffu, u.f.y, 8);
                u.f.x += __shfl_xor_sync(0xffffffffu, u.f.x, 16);
                u.f.y += __shfl_xor_sync(0xffffffffu, u.f.y, 16);
                if (lane < 4)
                    *(float2*)&pscol[(w & 3) * 128 + n0 + 8 * njj + 2 * t4] = u.f;
            }
            __syncthreads();
#pragma unroll
            for (int njj = 0; njj < 4; ++njj) {
                const int c0 = n0 + 8 * njj + 2 * t4;
                float2 a0 = *(const float2*)&pscol[c0];
                float2 a1 = *(const float2*)&pscol[128 + c0];
                float2 a2 = *(const float2*)&pscol[256 + c0];
                float2 a3 = *(const float2*)&pscol[384 + c0];
                F2U u;
                u.f.x = fminf(__fdividef(1.0f, a0.x + a1.x + a2.x + a3.x), 1.0f);
                u.f.y = fminf(__fdividef(1.0f, a0.y + a1.y + a2.y + a3.y), 1.0f);
                rv2[njj] = u.u;
            }
            // no 3rd barrier: pscol reads above precede each thread's arrival at
            // the next iteration's first barrier, which orders them against the
            // next pscol writes; rv2/lu4 are register-private.
        }

        // ---- X_new = lu * Xe * rv^T ----
        if (it + 1 < GROMOV_ITERS) {
#pragma unroll
            for (int mr = 0; mr < 4; ++mr) {
                const int r = m0 + 16 * (mr >> 1) + 8 * (mr & 1) + g;
                const ull L = splat2(lu4[mr]);
#pragma unroll
                for (int njj = 0; njj < 4; ++njj) {
                    const int c0 = n0 + 8 * njj + 2 * t4;
                    F2U u; u.u = mul2(mul2(L, xe2[mr * 4 + njj]), rv2[njj]);
                    __nv_bfloat16 h0, l0, h1, l1;
                    split_bf16(u.f.x, h0, l0); split_bf16(u.f.y, h1, l1);
                    *(u32*)(sb + O_XH + r * SB + c0 * 2) = packb(h0, h1);
                    *(u32*)(sb + O_XL + r * SB + c0 * 2) = packb(l0, l1);
                }
            }
        } else {
#pragma unroll
            for (int mr = 0; mr < 4; ++mr) {
                const int r = m0 + 16 * (mr >> 1) + 8 * (mr & 1) + g;
                const ull L = splat2(lu4[mr]);
#pragma unroll
                for (int njj = 0; njj < 4; ++njj) {
                    const int c0 = n0 + 8 * njj + 2 * t4;
                    F2U u; u.u = mul2(mul2(L, xe2[mr * 4 + njj]), rv2[njj]);
                    *(float2*)(outb + r * 128 + c0) = u.f;
                }
            }
        }
    }
}

extern "C" void kernel_launch(void* const* d_in, const int* in_sizes, int n_in,
                              void* d_out, int out_size)
{
    const float* X  = (const float*)d_in[0];
    const float* F1 = (const float*)d_in[1];
    const float* F2 = (const float*)d_in[2];
    const float* Kp = (const float*)d_in[3];
    float* out = (float*)d_out;

    int bs = in_sizes[0] / (128 * 128);
    if (bs > MAXB) bs = MAXB;

    prep_kernel<<<bs, THREADS>>>(F1, F2);

    cudaFuncSetAttribute(gw_kernel, cudaFuncAttributeMaxDynamicSharedMemorySize, SM_TOT);
    gw_kernel<<<bs, THREADS, SM_TOT>>>(X, Kp, out);
}

// round 8
// speedup vs baseline: 2.4981x; 1.0347x over previous
#include <cuda_runtime.h>
#include <cuda_bf16.h>
#include <cstdint>

#define TAU_F 0.1f
#define LOG2E_F 1.44269504f
#define GROMOV_ITERS 15
#define SINK_ITERS 15
#define THREADS 512
#define MAXB 2048
#define SB 272              // smem/global tile row stride (bytes), 128 bf16 cols + pad
#define TS 34816            // tile size bytes = 128*272

typedef unsigned long long ull;
typedef uint32_t u32;

// preconverted bf16 hi/lo tiles per batch: F2H, F2L, F1H, F1L (each TS bytes)
__device__ __align__(16) unsigned char g_tiles[(size_t)MAXB * 4 * TS];

// ---------------- helpers ----------------
__device__ __forceinline__ ull splat2(float x) {
    ull r; asm("mov.b64 %0, {%1, %1};" : "=l"(r) : "f"(x)); return r;
}
__device__ __forceinline__ void ffma2(ull &d, ull a, ull b) {
    asm("fma.rn.f32x2 %0, %1, %2, %0;" : "+l"(d) : "l"(a), "l"(b));
}
__device__ __forceinline__ ull mul2(ull a, ull b) {
    ull d; asm("mul.rn.f32x2 %0, %1, %2;" : "=l"(d) : "l"(a), "l"(b)); return d;
}
union F2U { ull u; float2 f; };
union B2U { __nv_bfloat162 b; u32 u; };

__device__ __forceinline__ void split_bf16(float x, __nv_bfloat16 &h, __nv_bfloat16 &l) {
    h = __float2bfloat16_rn(x);
    l = __float2bfloat16_rn(x - __bfloat162float(h));
}
__device__ __forceinline__ u32 packb(__nv_bfloat16 a, __nv_bfloat16 b) {
    B2U u; u.b = __nv_bfloat162(a, b); return u.u;
}
// pack (lo,hi) floats -> bf16x2 (hi goes to upper half)
__device__ __forceinline__ u32 cvt2(float hi, float lo) {
    u32 d; asm("cvt.rn.bf16x2.f32 %0, %1, %2;" : "=r"(d) : "f"(hi), "f"(lo)); return d;
}
__device__ __forceinline__ float bflo(u32 p) { return __uint_as_float(p << 16); }
__device__ __forceinline__ float bfhi(u32 p) { return __uint_as_float(p & 0xFFFF0000u); }
// pack hi+lo parts of a float pair: hp = packed hi, returns packed lo
__device__ __forceinline__ u32 lo_residual(u32 hp, float v0, float v1) {
    return cvt2(v1 - bfhi(hp), v0 - bflo(hp));
}

__device__ __forceinline__ u32 smem_u32(const void* p) {
    u32 a; asm("{ .reg .u64 t; cvta.to.shared.u64 t, %1; cvt.u32.u64 %0, t; }" : "=r"(a) : "l"(p));
    return a;
}

__device__ __forceinline__ void ldsm4(u32* r, u32 a) {
    asm volatile("ldmatrix.sync.aligned.m8n8.x4.shared.b16 {%0,%1,%2,%3}, [%4];"
                 : "=r"(r[0]), "=r"(r[1]), "=r"(r[2]), "=r"(r[3]) : "r"(a));
}
__device__ __forceinline__ void ldsm4t(u32* r, u32 a) {
    asm volatile("ldmatrix.sync.aligned.m8n8.x4.trans.shared.b16 {%0,%1,%2,%3}, [%4];"
                 : "=r"(r[0]), "=r"(r[1]), "=r"(r[2]), "=r"(r[3]) : "r"(a));
}
__device__ __forceinline__ void stsm4(u32 a, u32 r0, u32 r1, u32 r2, u32 r3) {
    asm volatile("stmatrix.sync.aligned.m8n8.x4.shared.b16 [%0], {%1,%2,%3,%4};"
                 :: "r"(a), "r"(r0), "r"(r1), "r"(r2), "r"(r3) : "memory");
}
__device__ __forceinline__ void hmma(float* d, u32 a0, u32 a1, u32 a2, u32 a3,
                                     u32 b0, u32 b1) {
    asm volatile("mma.sync.aligned.m16n8k16.row.col.f32.bf16.bf16.f32 "
                 "{%0,%1,%2,%3}, {%4,%5,%6,%7}, {%8,%9}, {%0,%1,%2,%3};"
                 : "+f"(d[0]), "+f"(d[1]), "+f"(d[2]), "+f"(d[3])
                 : "r"(a0), "r"(a1), "r"(a2), "r"(a3), "r"(b0), "r"(b1));
}
__device__ __forceinline__ void mma_blk(float* acc, int njj0, const u32* a8, const u32* b) {
    hmma(acc + (njj0)     * 4, a8[0], a8[1], a8[2], a8[3], b[0], b[1]);
    hmma(acc + (njj0 + 1) * 4, a8[0], a8[1], a8[2], a8[3], b[2], b[3]);
    hmma(acc + (4 + njj0)     * 4, a8[4], a8[5], a8[6], a8[7], b[0], b[1]);
    hmma(acc + (4 + njj0 + 1) * 4, a8[4], a8[5], a8[6], a8[7], b[2], b[3]);
}

#define CP_COMMIT() asm volatile("cp.async.commit_group;" ::: "memory")
#define CP_WAIT0()  asm volatile("cp.async.wait_group 0;" ::: "memory")
__device__ __forceinline__ void cp16(u32 saddr, const void* g) {
    asm volatile("cp.async.cg.shared.global [%0], [%1], 16;" :: "r"(saddr), "l"(g) : "memory");
}
__device__ __forceinline__ void nbar(int id) {
    asm volatile("bar.sync %0, 128;" :: "r"(id) : "memory");
}

// ---------------- smem layout (byte offsets) ----------------
#define O_XH   0
#define O_XL   (TS)
#define O_F2H  (2*TS)       // Z overwrites here after G12; cp.async refills post-G34
#define O_F2L  (3*TS)
#define O_F1H  (4*TS)
#define O_F1L  (5*TS)
#define O_PSR  (6*TS)            // psrow[2][128][4] float (parity double-buffer)
#define O_PSC  (O_PSR + 4096)    // pscol[2][128][4] float
#define O_RED  (O_PSC + 4096)    // red[16] float
#define SM_TOT (O_RED + 128)

// ===================== prep: split F1/F2 to bf16 hi/lo padded tiles =====================
__global__ __launch_bounds__(THREADS, 1)
void prep_kernel(const float* __restrict__ F1g, const float* __restrict__ F2g)
{
    const int t = threadIdx.x, b = blockIdx.x;
    const int row = t >> 2, cb = (t & 3) * 32;
    unsigned char* ob = g_tiles + (size_t)b * 4 * TS;
#pragma unroll
    for (int m = 0; m < 2; ++m) {
        const float* src = (m ? F1g : F2g) + (size_t)b * 16384;
        unsigned char* dH = ob + (size_t)(m ? 2 : 0) * TS + row * SB;
        unsigned char* dL = dH + TS;
#pragma unroll
        for (int q = 0; q < 8; ++q) {
            float4 v = *(const float4*)(src + row * 128 + cb + 4 * q);
            __nv_bfloat16 h0, l0, h1, l1, h2, l2, h3, l3;
            split_bf16(v.x, h0, l0); split_bf16(v.y, h1, l1);
            split_bf16(v.z, h2, l2); split_bf16(v.w, h3, l3);
            *(uint2*)(dH + (cb + 4 * q) * 2) = make_uint2(packb(h0, h1), packb(h2, h3));
            *(uint2*)(dL + (cb + 4 * q) * 2) = make_uint2(packb(l0, l1), packb(l2, l3));
        }
    }
}

// ===================== main kernel =====================
__global__ __launch_bounds__(THREADS, 1)
void gw_kernel(const float* __restrict__ Xg, const float* __restrict__ Kpg,
               float* __restrict__ outg)
{
    extern __shared__ __align__(128) unsigned char sb[];
    const u32 sbu = smem_u32(sb);
    float* red = (float*)(sb + O_RED);

    const int t = threadIdx.x;
    const int w = t >> 5, lane = t & 31;
    const int g = lane >> 2, t4 = lane & 3;
    const int m0 = (w & 3) * 32, n0 = (w >> 2) * 32;
    const int b = blockIdx.x;

    const float* Xb = Xg  + (size_t)b * 16384;
    const float* Kp = Kpg + (size_t)b * 16384;
    float* outb     = outg + (size_t)b * 16384;
    const unsigned char* gb = g_tiles + (size_t)b * 4 * TS;

    // ldmatrix lane-pattern offsets (bytes)
    const int l = lane;
    const u32 pA  = (u32)((l & 15) * SB + ((l >> 4) << 3) * 2);
    const u32 pAT = (u32)(((l & 7) + ((l >> 4) << 3)) * SB + ((l >> 3) & 1) * 16);
    const u32 pBt = (u32)(((l & 7) + (((l >> 3) & 1) << 3)) * SB + ((l >> 4) << 3) * 2);
    const u32 pBn = (u32)(((l & 7) + ((l >> 4) << 3)) * SB + (((l >> 3) & 1) << 3) * 2);

    // warp base addresses
    const u32 aXH  = sbu + O_XH  + m0 * SB + pA;
    const u32 aXL  = sbu + O_XL  + m0 * SB + pA;
    const u32 aF1H = sbu + O_F1H + m0 * SB + pA;
    const u32 aF1L = sbu + O_F1L + m0 * SB + pA;
    const u32 atF1H = sbu + O_F1H + m0 * 2 + pAT;
    const u32 atF1L = sbu + O_F1L + m0 * 2 + pAT;
    const u32 btXH = sbu + O_XH  + n0 * 2 + pBt;   // Y after overwrite
    const u32 btXL = sbu + O_XL  + n0 * 2 + pBt;
    const u32 btF2H = sbu + O_F2H + n0 * 2 + pBt;  // F2 (G12) / Z (G34)
    const u32 btF2L = sbu + O_F2L + n0 * 2 + pBt;
    const u32 bnF2H = sbu + O_F2H + n0 * SB + pBn;
    const u32 bnF2L = sbu + O_F2L + n0 * SB + pBn;

    // stmatrix base (X tile); per (mi,rh) add (16*mi+8*rh)*SB
    const u32 stX = sbu + O_XH + (m0 + (lane & 7)) * SB + (n0 + ((lane >> 3) << 3)) * 2;

    // ---- prologue: X -> bf16 hi/lo tile; prefetch F2/F1 tiles ----
    {
        const int row = t >> 2, cb = (t & 3) * 32;
        unsigned char* dH = sb + O_XH + row * SB;
        unsigned char* dL = sb + O_XL + row * SB;
#pragma unroll
        for (int q = 0; q < 8; ++q) {
            float4 v = *(const float4*)(Xb + row * 128 + cb + 4 * q);
            __nv_bfloat16 h0, l0, h1, l1, h2, l2, h3, l3;
            split_bf16(v.x, h0, l0); split_bf16(v.y, h1, l1);
            split_bf16(v.z, h2, l2); split_bf16(v.w, h3, l3);
            *(uint2*)(dH + (cb + 4 * q) * 2) = make_uint2(packb(h0, h1), packb(h2, h3));
            *(uint2*)(dL + (cb + 4 * q) * 2) = make_uint2(packb(l0, l1), packb(l2, l3));
        }
    }
    for (int i = t; i < 4 * TS / 16; i += THREADS)
        cp16(sbu + O_F2H + i * 16, gb + i * 16);
    CP_COMMIT();

    float accY[32], accZ[32], acc[32];
    ull xe2[16], rv2[4];
    float lu4[4];

    for (int it = 0; it < GROMOV_ITERS; ++it) {
        CP_WAIT0();
        __syncthreads();

        // ====== G12: Y = X*F2, Z = X*F2^T  (3-term split: hh + lh + hl) ======
#pragma unroll
        for (int q = 0; q < 32; ++q) { accY[q] = 0.0f; accZ[q] = 0.0f; }
#pragma unroll 1
        for (int kk = 0; kk < 8; ++kk) {
            const u32 kb = kk * 32, krb = kk * 16 * SB;
            u32 ah[8], al[8], bq[4];
            ldsm4(ah,     aXH + kb); ldsm4(ah + 4, aXH + 16 * SB + kb);
            ldsm4(al,     aXL + kb); ldsm4(al + 4, aXL + 16 * SB + kb);
#pragma unroll
            for (int h2 = 0; h2 < 2; ++h2) {
                ldsm4t(bq, btF2H + krb + h2 * 32);
                mma_blk(accY, 2 * h2, ah, bq); mma_blk(accY, 2 * h2, al, bq);
                ldsm4t(bq, btF2L + krb + h2 * 32);
                mma_blk(accY, 2 * h2, ah, bq);
                ldsm4(bq, bnF2H + h2 * 16 * SB + kb);
                mma_blk(accZ, 2 * h2, ah, bq); mma_blk(accZ, 2 * h2, al, bq);
                ldsm4(bq, bnF2L + h2 * 16 * SB + kb);
                mma_blk(accZ, 2 * h2, ah, bq);
            }
        }
        __syncthreads();
        // store Y -> X slots, Z -> F2 slots (bf16 hi/lo via stmatrix)
#pragma unroll
        for (int mi = 0; mi < 2; ++mi)
#pragma unroll
            for (int rh = 0; rh < 2; ++rh) {
                u32 yh[4], yl[4], zh[4], zl[4];
#pragma unroll
                for (int njj = 0; njj < 4; ++njj) {
                    const float* y = accY + (mi * 4 + njj) * 4 + 2 * rh;
                    const float* z = accZ + (mi * 4 + njj) * 4 + 2 * rh;
                    yh[njj] = cvt2(y[1], y[0]);
                    yl[njj] = lo_residual(yh[njj], y[0], y[1]);
                    zh[njj] = cvt2(z[1], z[0]);
                    zl[njj] = lo_residual(zh[njj], z[0], z[1]);
                }
                const u32 ad = stX + (16 * mi + 8 * rh) * SB;
                stsm4(ad,          yh[0], yh[1], yh[2], yh[3]);
                stsm4(ad + TS,     yl[0], yl[1], yl[2], yl[3]);
                stsm4(ad + 2 * TS, zh[0], zh[1], zh[2], zh[3]);
                stsm4(ad + 3 * TS, zl[0], zl[1], zl[2], zl[3]);
            }
        __syncthreads();

        // ====== G34: C = Kp + F1*Y + F1^T*Z  (3-term split) ======
#pragma unroll
        for (int mi = 0; mi < 2; ++mi)
#pragma unroll
            for (int njj = 0; njj < 4; ++njj) {
                float* d = acc + (mi * 4 + njj) * 4;
                const int c0 = n0 + 8 * njj + 2 * t4;
                float2 kA = *(const float2*)(Kp + (m0 + 16 * mi + g) * 128 + c0);
                float2 kB = *(const float2*)(Kp + (m0 + 16 * mi + 8 + g) * 128 + c0);
                d[0] = kA.x; d[1] = kA.y; d[2] = kB.x; d[3] = kB.y;
            }
#pragma unroll 1
        for (int kk = 0; kk < 8; ++kk) {
            const u32 kb = kk * 32, krb = kk * 16 * SB;
            u32 ah[8], al[8], bq[4];
            // C += F1 * Y
            ldsm4(ah,     aF1H + kb); ldsm4(ah + 4, aF1H + 16 * SB + kb);
            ldsm4(al,     aF1L + kb); ldsm4(al + 4, aF1L + 16 * SB + kb);
#pragma unroll
            for (int h2 = 0; h2 < 2; ++h2) {
                ldsm4t(bq, btXH + krb + h2 * 32);
                mma_blk(acc, 2 * h2, ah, bq); mma_blk(acc, 2 * h2, al, bq);
                ldsm4t(bq, btXL + krb + h2 * 32);
                mma_blk(acc, 2 * h2, ah, bq);
            }
            // C += F1^T * Z
            ldsm4t(ah,     atF1H + krb); ldsm4t(ah + 4, atF1H + krb + 32);
            ldsm4t(al,     atF1L + krb); ldsm4t(al + 4, atF1L + krb + 32);
#pragma unroll
            for (int h2 = 0; h2 < 2; ++h2) {
                ldsm4t(bq, btF2H + krb + h2 * 32);
                mma_blk(acc, 2 * h2, ah, bq); mma_blk(acc, 2 * h2, al, bq);
                ldsm4t(bq, btF2L + krb + h2 * 32);
                mma_blk(acc, 2 * h2, ah, bq);
            }
        }
        __syncthreads();

        // prefetch next iter's F2/F1 (overwrites Z + F1 slots; disjoint from epilogue)
        if (it + 1 < GROMOV_ITERS) {
            for (int i = t; i < 4 * TS / 16; i += THREADS)
                cp16(sbu + O_F2H + i * 16, gb + i * 16);
            CP_COMMIT();
        }

        // ---- L-inf norm (single barrier; all threads reduce the 16 maxima) ----
        float mx = 0.0f;
#pragma unroll
        for (int q = 0; q < 32; ++q) mx = fmaxf(mx, fabsf(acc[q]));
#pragma unroll
        for (int off = 16; off > 0; off >>= 1)
            mx = fmaxf(mx, __shfl_xor_sync(0xffffffffu, mx, off));
        if (lane == 0) red[w] = mx;
        __syncthreads();
        float scale2;
        {
            float4 r0 = *(const float4*)&red[0];
            float4 r1 = *(const float4*)&red[4];
            float4 r2 = *(const float4*)&red[8];
            float4 r3 = *(const float4*)&red[12];
            float n = fmaxf(fmaxf(fmaxf(r0.x, r0.y), fmaxf(r0.z, r0.w)),
                    fmaxf(fmaxf(fmaxf(r1.x, r1.y), fmaxf(r1.z, r1.w)),
                    fmaxf(fmaxf(fmaxf(r2.x, r2.y), fmaxf(r2.z, r2.w)),
                          fmaxf(fmaxf(r3.x, r3.y), fmaxf(r3.z, r3.w)))));
            scale2 = __fdividef(1.0f, n * TAU_F) * LOG2E_F;
        }

        // ---- Xe = exp2(C*scale2) in registers; frag layout [mi*2+rh][njj] pairs ----
#pragma unroll
        for (int mi = 0; mi < 2; ++mi)
#pragma unroll
            for (int rh = 0; rh < 2; ++rh)
#pragma unroll
                for (int njj = 0; njj < 4; ++njj) {
                    const float* d = acc + (mi * 4 + njj) * 4 + 2 * rh;
                    F2U u;
                    u.f.x = exp2f(d[0] * scale2);
                    u.f.y = exp2f(d[1] * scale2);
                    xe2[(mi * 2 + rh) * 4 + njj] = u.u;
                }
#pragma unroll
        for (int njj = 0; njj < 4; ++njj) rv2[njj] = splat2(1.0f);

        // ---- Sinkhorn: named sub-barriers, parity double-buffered partials ----
        for (int sit = 0; sit < SINK_ITERS; ++sit) {
            float* prow = (float*)(sb + O_PSR) + (sit & 1) * 512;
            float* pcol = (float*)(sb + O_PSC) + (sit & 1) * 512;
            // row sums (couples warps with same w&3; slices indexed by w>>2)
#pragma unroll
            for (int mr = 0; mr < 4; ++mr) {
                ull s2 = 0ull;
#pragma unroll
                for (int njj = 0; njj < 4; ++njj) ffma2(s2, xe2[mr * 4 + njj], rv2[njj]);
                F2U u; u.u = s2;
                float s = u.f.x + u.f.y;
                s += __shfl_xor_sync(0xffffffffu, s, 1);
                s += __shfl_xor_sync(0xffffffffu, s, 2);
                if (t4 == 0) {
                    const int r = m0 + 16 * (mr >> 1) + 8 * (mr & 1) + g;
                    prow[r * 4 + (w >> 2)] = s;
                }
            }
            nbar(1 + (w & 3));
#pragma unroll
            for (int mr = 0; mr < 4; ++mr) {
                const int r = m0 + 16 * (mr >> 1) + 8 * (mr & 1) + g;
                float4 v = *(const float4*)&prow[r * 4];
                lu4[mr] = __fdividef(1.0f, (v.x + v.y) + (v.z + v.w));
            }
            // col sums (couples warps with same w>>2; slices indexed by w&3)
#pragma unroll
            for (int njj = 0; njj < 4; ++njj) {
                ull cs = 0ull;
#pragma unroll
                for (int mr = 0; mr < 4; ++mr) ffma2(cs, xe2[mr * 4 + njj], splat2(lu4[mr]));
                F2U u; u.u = cs;
                u.f.x += __shfl_xor_sync(0xffffffffu, u.f.x, 4);
                u.f.y += __shfl_xor_sync(0xffffffffu, u.f.y, 4);
                u.f.x += __shfl_xor_sync(0xffffffffu, u.f.x, 8);
                u.f.y += __shfl_xor_sync(0xffffffffu, u.f.y, 8);
                u.f.x += __shfl_xor_sync(0xffffffffu, u.f.x, 16);
                u.f.y += __shfl_xor_sync(0xffffffffu, u.f.y, 16);
                if (lane < 4) {
                    const int c0 = n0 + 8 * njj + 2 * t4;
                    pcol[c0 * 4 + (w & 3)]       = u.f.x;
                    pcol[(c0 + 1) * 4 + (w & 3)] = u.f.y;
                }
            }
            nbar(5 + (w >> 2));
#pragma unroll
            for (int njj = 0; njj < 4; ++njj) {
                const int c0 = n0 + 8 * njj + 2 * t4;
                float4 a0 = *(const float4*)&pcol[c0 * 4];
                float4 a1 = *(const float4*)&pcol[(c0 + 1) * 4];
                F2U u;
                u.f.x = fminf(__fdividef(1.0f, (a0.x + a0.y) + (a0.z + a0.w)), 1.0f);
                u.f.y = fminf(__fdividef(1.0f, (a1.x + a1.y) + (a1.z + a1.w)), 1.0f);
                rv2[njj] = u.u;
            }
        }

        // ---- X_new = lu * Xe * rv^T ----
        if (it + 1 < GROMOV_ITERS) {
#pragma unroll
            for (int mr = 0; mr < 4; ++mr) {
                const ull L = splat2(lu4[mr]);
                u32 xh[4], xl[4];
#pragma unroll
                for (int njj = 0; njj < 4; ++njj) {
                    F2U u; u.u = mul2(mul2(L, xe2[mr * 4 + njj]), rv2[njj]);
                    xh[njj] = cvt2(u.f.y, u.f.x);
                    xl[njj] = lo_residual(xh[njj], u.f.x, u.f.y);
                }
                const u32 ad = stX + (16 * (mr >> 1) + 8 * (mr & 1)) * SB;
                stsm4(ad,      xh[0], xh[1], xh[2], xh[3]);
                stsm4(ad + TS, xl[0], xl[1], xl[2], xl[3]);
            }
        } else {
#pragma unroll
            for (int mr = 0; mr < 4; ++mr) {
                const int r = m0 + 16 * (mr >> 1) + 8 * (mr & 1) + g;
                const ull L = splat2(lu4[mr]);
#pragma unroll
                for (int njj = 0; njj < 4; ++njj) {
                    const int c0 = n0 + 8 * njj + 2 * t4;
                    F2U u; u.u = mul2(mul2(L, xe2[mr * 4 + njj]), rv2[njj]);
                    *(float2*)(outb + r * 128 + c0) = u.f;
                }
            }
        }
    }
}

extern "C" void kernel_launch(void* const* d_in, const int* in_sizes, int n_in,
                              void* d_out, int out_size)
{
    const float* X  = (const float*)d_in[0];
    const float* F1 = (const float*)d_in[1];
    const float* F2 = (const float*)d_in[2];
    const float* Kp = (const float*)d_in[3];
    float* out = (float*)d_out;

    int bs = in_sizes[0] / (128 * 128);
    if (bs > MAXB) bs = MAXB;

    prep_kernel<<<bs, THREADS>>>(F1, F2);

    cudaFuncSetAttribute(gw_kernel, cudaFuncAttributeMaxDynamicSharedMemorySize, SM_TOT);
    gw_kernel<<<bs, THREADS, SM_TOT>>>(X, Kp, out);
}

// round 9
// speedup vs baseline: 2.5040x; 1.0024x over previous
#include <cuda_runtime.h>
#include <cuda_bf16.h>
#include <cstdint>

#define TAU_F 0.1f
#define LOG2E_F 1.44269504f
#define GROMOV_ITERS 15
#define SINK_ITERS 15
#define THREADS 512
#define MAXB 2048
#define SB 272              // smem/global tile row stride (bytes), 128 bf16 cols + pad
#define TS 34816            // tile size bytes = 128*272

typedef unsigned long long ull;
typedef uint32_t u32;

// preconverted bf16 hi/lo tiles per batch: F2H, F2L, F1H, F1L (each TS bytes)
__device__ __align__(16) unsigned char g_tiles[(size_t)MAXB * 4 * TS];

// ---------------- helpers ----------------
__device__ __forceinline__ ull splat2(float x) {
    ull r; asm("mov.b64 %0, {%1, %1};" : "=l"(r) : "f"(x)); return r;
}
__device__ __forceinline__ void ffma2(ull &d, ull a, ull b) {
    asm("fma.rn.f32x2 %0, %1, %2, %0;" : "+l"(d) : "l"(a), "l"(b));
}
__device__ __forceinline__ ull mul2(ull a, ull b) {
    ull d; asm("mul.rn.f32x2 %0, %1, %2;" : "=l"(d) : "l"(a), "l"(b)); return d;
}
union F2U { ull u; float2 f; };
union B2U { __nv_bfloat162 b; u32 u; };

__device__ __forceinline__ void split_bf16(float x, __nv_bfloat16 &h, __nv_bfloat16 &l) {
    h = __float2bfloat16_rn(x);
    l = __float2bfloat16_rn(x - __bfloat162float(h));
}
__device__ __forceinline__ u32 packb(__nv_bfloat16 a, __nv_bfloat16 b) {
    B2U u; u.b = __nv_bfloat162(a, b); return u.u;
}
__device__ __forceinline__ u32 cvt2(float hi, float lo) {
    u32 d; asm("cvt.rn.bf16x2.f32 %0, %1, %2;" : "=r"(d) : "f"(hi), "f"(lo)); return d;
}
__device__ __forceinline__ float bflo(u32 p) { return __uint_as_float(p << 16); }
__device__ __forceinline__ float bfhi(u32 p) { return __uint_as_float(p & 0xFFFF0000u); }
__device__ __forceinline__ u32 lo_residual(u32 hp, float v0, float v1) {
    return cvt2(v1 - bfhi(hp), v0 - bflo(hp));
}

__device__ __forceinline__ u32 smem_u32(const void* p) {
    u32 a; asm("{ .reg .u64 t; cvta.to.shared.u64 t, %1; cvt.u32.u64 %0, t; }" : "=r"(a) : "l"(p));
    return a;
}

__device__ __forceinline__ void ldsm4(u32* r, u32 a) {
    asm volatile("ldmatrix.sync.aligned.m8n8.x4.shared.b16 {%0,%1,%2,%3}, [%4];"
                 : "=r"(r[0]), "=r"(r[1]), "=r"(r[2]), "=r"(r[3]) : "r"(a));
}
__device__ __forceinline__ void ldsm4t(u32* r, u32 a) {
    asm volatile("ldmatrix.sync.aligned.m8n8.x4.trans.shared.b16 {%0,%1,%2,%3}, [%4];"
                 : "=r"(r[0]), "=r"(r[1]), "=r"(r[2]), "=r"(r[3]) : "r"(a));
}
__device__ __forceinline__ void stsm4(u32 a, u32 r0, u32 r1, u32 r2, u32 r3) {
    asm volatile("stmatrix.sync.aligned.m8n8.x4.shared.b16 [%0], {%1,%2,%3,%4};"
                 :: "r"(a), "r"(r0), "r"(r1), "r"(r2), "r"(r3) : "memory");
}
__device__ __forceinline__ void hmma(float* d, u32 a0, u32 a1, u32 a2, u32 a3,
                                     u32 b0, u32 b1) {
    asm volatile("mma.sync.aligned.m16n8k16.row.col.f32.bf16.bf16.f32 "
                 "{%0,%1,%2,%3}, {%4,%5,%6,%7}, {%8,%9}, {%0,%1,%2,%3};"
                 : "+f"(d[0]), "+f"(d[1]), "+f"(d[2]), "+f"(d[3])
                 : "r"(a0), "r"(a1), "r"(a2), "r"(a3), "r"(b0), "r"(b1));
}
__device__ __forceinline__ void mma_blk(float* acc, int njj0, const u32* a8, const u32* b) {
    hmma(acc + (njj0)     * 4, a8[0], a8[1], a8[2], a8[3], b[0], b[1]);
    hmma(acc + (njj0 + 1) * 4, a8[0], a8[1], a8[2], a8[3], b[2], b[3]);
    hmma(acc + (4 + njj0)     * 4, a8[4], a8[5], a8[6], a8[7], b[0], b[1]);
    hmma(acc + (4 + njj0 + 1) * 4, a8[4], a8[5], a8[6], a8[7], b[2], b[3]);
}

// One single-accumulator GEMM pass, 3-term split (hh + lh + hl).
// Per kk: all 8 LDSM issued upfront (MLP), then 24 HMMA. unroll 2 lets ptxas
// hoist kk+1 loads into kk's mma stream.
template<bool AT, bool BT>
__device__ __forceinline__ void gemm_pass(float* acc,
    u32 aH, u32 aL, u32 aStep, u32 aOff2,
    u32 bH, u32 bL, u32 bStep, u32 bOff2)
{
#pragma unroll 2
    for (int kk = 0; kk < 8; ++kk) {
        u32 ah[8], al[8], bh[8], bl[8];
        if (AT) { ldsm4t(ah, aH); ldsm4t(ah + 4, aH + aOff2);
                  ldsm4t(al, aL); ldsm4t(al + 4, aL + aOff2); }
        else    { ldsm4(ah, aH);  ldsm4(ah + 4, aH + aOff2);
                  ldsm4(al, aL);  ldsm4(al + 4, aL + aOff2); }
        if (BT) { ldsm4t(bh, bH); ldsm4t(bh + 4, bH + bOff2);
                  ldsm4t(bl, bL); ldsm4t(bl + 4, bL + bOff2); }
        else    { ldsm4(bh, bH);  ldsm4(bh + 4, bH + bOff2);
                  ldsm4(bl, bL);  ldsm4(bl + 4, bL + bOff2); }
        mma_blk(acc, 0, ah, bh);     mma_blk(acc, 0, al, bh);     mma_blk(acc, 0, ah, bl);
        mma_blk(acc, 2, ah, bh + 4); mma_blk(acc, 2, al, bh + 4); mma_blk(acc, 2, ah, bl + 4);
        aH += aStep; aL += aStep; bH += bStep; bL += bStep;
    }
}

#define CP_COMMIT() asm volatile("cp.async.commit_group;" ::: "memory")
#define CP_WAIT0()  asm volatile("cp.async.wait_group 0;" ::: "memory")
__device__ __forceinline__ void cp16(u32 saddr, const void* g) {
    asm volatile("cp.async.cg.shared.global [%0], [%1], 16;" :: "r"(saddr), "l"(g) : "memory");
}
__device__ __forceinline__ void nbar(int id) {
    asm volatile("bar.sync %0, 128;" :: "r"(id) : "memory");
}

// ---------------- smem layout (byte offsets) ----------------
#define O_XH   0
#define O_XL   (TS)
#define O_F2H  (2*TS)       // Z overwrites here after G12; cp.async refills post-G34
#define O_F2L  (3*TS)
#define O_F1H  (4*TS)       // loaded once in prologue, never overwritten
#define O_F1L  (5*TS)
#define O_PSR  (6*TS)            // psrow[2][128][4] float (parity double-buffer)
#define O_PSC  (O_PSR + 4096)    // pscol[2][128][4] float
#define O_RED  (O_PSC + 4096)    // red[16] float
#define SM_TOT (O_RED + 128)

// ===================== prep: split F1/F2 to bf16 hi/lo padded tiles =====================
__global__ __launch_bounds__(THREADS, 1)
void prep_kernel(const float* __restrict__ F1g, const float* __restrict__ F2g)
{
    const int t = threadIdx.x, b = blockIdx.x;
    const int row = t >> 2, cb = (t & 3) * 32;
    unsigned char* ob = g_tiles + (size_t)b * 4 * TS;
#pragma unroll
    for (int m = 0; m < 2; ++m) {
        const float* src = (m ? F1g : F2g) + (size_t)b * 16384;
        unsigned char* dH = ob + (size_t)(m ? 2 : 0) * TS + row * SB;
        unsigned char* dL = dH + TS;
#pragma unroll
        for (int q = 0; q < 8; ++q) {
            float4 v = *(const float4*)(src + row * 128 + cb + 4 * q);
            __nv_bfloat16 h0, l0, h1, l1, h2, l2, h3, l3;
            split_bf16(v.x, h0, l0); split_bf16(v.y, h1, l1);
            split_bf16(v.z, h2, l2); split_bf16(v.w, h3, l3);
            *(uint2*)(dH + (cb + 4 * q) * 2) = make_uint2(packb(h0, h1), packb(h2, h3));
            *(uint2*)(dL + (cb + 4 * q) * 2) = make_uint2(packb(l0, l1), packb(l2, l3));
        }
    }
}

// ===================== main kernel =====================
__global__ __launch_bounds__(THREADS, 1)
void gw_kernel(const float* __restrict__ Xg, const float* __restrict__ Kpg,
               float* __restrict__ outg)
{
    extern __shared__ __align__(128) unsigned char sb[];
    const u32 sbu = smem_u32(sb);
    float* red = (float*)(sb + O_RED);

    const int t = threadIdx.x;
    const int w = t >> 5, lane = t & 31;
    const int g = lane >> 2, t4 = lane & 3;
    const int m0 = (w & 3) * 32, n0 = (w >> 2) * 32;
    const int b = blockIdx.x;

    const float* Xb = Xg  + (size_t)b * 16384;
    const float* Kp = Kpg + (size_t)b * 16384;
    float* outb     = outg + (size_t)b * 16384;
    const unsigned char* gb = g_tiles + (size_t)b * 4 * TS;

    // ldmatrix lane-pattern offsets (bytes)
    const int l = lane;
    const u32 pA  = (u32)((l & 15) * SB + ((l >> 4) << 3) * 2);
    const u32 pAT = (u32)(((l & 7) + ((l >> 4) << 3)) * SB + ((l >> 3) & 1) * 16);
    const u32 pBt = (u32)(((l & 7) + (((l >> 3) & 1) << 3)) * SB + ((l >> 4) << 3) * 2);
    const u32 pBn = (u32)(((l & 7) + ((l >> 4) << 3)) * SB + (((l >> 3) & 1) << 3) * 2);

    // warp base addresses
    const u32 aXH  = sbu + O_XH  + m0 * SB + pA;
    const u32 aXL  = sbu + O_XL  + m0 * SB + pA;
    const u32 aF1H = sbu + O_F1H + m0 * SB + pA;
    const u32 aF1L = sbu + O_F1L + m0 * SB + pA;
    const u32 atF1H = sbu + O_F1H + m0 * 2 + pAT;
    const u32 atF1L = sbu + O_F1L + m0 * 2 + pAT;
    const u32 btXH = sbu + O_XH  + n0 * 2 + pBt;   // Y after overwrite
    const u32 btXL = sbu + O_XL  + n0 * 2 + pBt;
    const u32 btF2H = sbu + O_F2H + n0 * 2 + pBt;  // F2 (G12) / Z (G34)
    const u32 btF2L = sbu + O_F2L + n0 * 2 + pBt;
    const u32 bnF2H = sbu + O_F2H + n0 * SB + pBn;
    const u32 bnF2L = sbu + O_F2L + n0 * SB + pBn;

    // stmatrix base (X tile); per (mi,rh) add (16*mi+8*rh)*SB
    const u32 stX = sbu + O_XH + (m0 + (lane & 7)) * SB + (n0 + ((lane >> 3) << 3)) * 2;

    // ---- prologue: X -> bf16 hi/lo tile; prefetch all 4 F tiles ----
    {
        const int row = t >> 2, cb = (t & 3) * 32;
        unsigned char* dH = sb + O_XH + row * SB;
        unsigned char* dL = sb + O_XL + row * SB;
#pragma unroll
        for (int q = 0; q < 8; ++q) {
            float4 v = *(const float4*)(Xb + row * 128 + cb + 4 * q);
            __nv_bfloat16 h0, l0, h1, l1, h2, l2, h3, l3;
            split_bf16(v.x, h0, l0); split_bf16(v.y, h1, l1);
            split_bf16(v.z, h2, l2); split_bf16(v.w, h3, l3);
            *(uint2*)(dH + (cb + 4 * q) * 2) = make_uint2(packb(h0, h1), packb(h2, h3));
            *(uint2*)(dL + (cb + 4 * q) * 2) = make_uint2(packb(l0, l1), packb(l2, l3));
        }
    }
    for (int i = t; i < 4 * TS / 16; i += THREADS)
        cp16(sbu + O_F2H + i * 16, gb + i * 16);
    CP_COMMIT();

    float accY[32], accZ[32], acc[32];
    ull xe2[16], rv2[4];
    float lu4[4];

    for (int it = 0; it < GROMOV_ITERS; ++it) {
        CP_WAIT0();
        __syncthreads();

        // ====== G12: Y = X*F2 (pass 1), Z = X*F2^T (pass 2) ======
#pragma unroll
        for (int q = 0; q < 32; ++q) accY[q] = 0.0f;
        gemm_pass<false, true>(accY, aXH, aXL, 32, 16 * SB,
                               btF2H, btF2L, 16 * SB, 32);
#pragma unroll
        for (int q = 0; q < 32; ++q) accZ[q] = 0.0f;
        gemm_pass<false, false>(accZ, aXH, aXL, 32, 16 * SB,
                                bnF2H, bnF2L, 32, 16 * SB);
        __syncthreads();
        // store Y -> X slots, Z -> F2 slots (bf16 hi/lo via stmatrix)
#pragma unroll
        for (int mi = 0; mi < 2; ++mi)
#pragma unroll
            for (int rh = 0; rh < 2; ++rh) {
                u32 yh[4], yl[4], zh[4], zl[4];
#pragma unroll
                for (int njj = 0; njj < 4; ++njj) {
                    const float* y = accY + (mi * 4 + njj) * 4 + 2 * rh;
                    const float* z = accZ + (mi * 4 + njj) * 4 + 2 * rh;
                    yh[njj] = cvt2(y[1], y[0]);
                    yl[njj] = lo_residual(yh[njj], y[0], y[1]);
                    zh[njj] = cvt2(z[1], z[0]);
                    zl[njj] = lo_residual(zh[njj], z[0], z[1]);
                }
                const u32 ad = stX + (16 * mi + 8 * rh) * SB;
                stsm4(ad,          yh[0], yh[1], yh[2], yh[3]);
                stsm4(ad + TS,     yl[0], yl[1], yl[2], yl[3]);
                stsm4(ad + 2 * TS, zh[0], zh[1], zh[2], zh[3]);
                stsm4(ad + 3 * TS, zl[0], zl[1], zl[2], zl[3]);
            }
        __syncthreads();

        // ====== G34: C = Kp + F1*Y (pass 1) + F1^T*Z (pass 2) ======
#pragma unroll
        for (int mi = 0; mi < 2; ++mi)
#pragma unroll
            for (int njj = 0; njj < 4; ++njj) {
                float* d = acc + (mi * 4 + njj) * 4;
                const int c0 = n0 + 8 * njj + 2 * t4;
                float2 kA = *(const float2*)(Kp + (m0 + 16 * mi + g) * 128 + c0);
                float2 kB = *(const float2*)(Kp + (m0 + 16 * mi + 8 + g) * 128 + c0);
                d[0] = kA.x; d[1] = kA.y; d[2] = kB.x; d[3] = kB.y;
            }
        gemm_pass<false, true>(acc, aF1H, aF1L, 32, 16 * SB,
                               btXH, btXL, 16 * SB, 32);
        gemm_pass<true, true>(acc, atF1H, atF1L, 16 * SB, 32,
                              btF2H, btF2L, 16 * SB, 32);
        __syncthreads();

        // prefetch next iter's F2 only (F1 slots never overwritten)
        if (it + 1 < GROMOV_ITERS) {
            for (int i = t; i < 2 * TS / 16; i += THREADS)
                cp16(sbu + O_F2H + i * 16, gb + i * 16);
            CP_COMMIT();
        }

        // ---- L-inf norm ----
        float mx = 0.0f;
#pragma unroll
        for (int q = 0; q < 32; ++q) mx = fmaxf(mx, fabsf(acc[q]));
#pragma unroll
        for (int off = 16; off > 0; off >>= 1)
            mx = fmaxf(mx, __shfl_xor_sync(0xffffffffu, mx, off));
        if (lane == 0) red[w] = mx;
        __syncthreads();
        float scale2;
        {
            float4 r0 = *(const float4*)&red[0];
            float4 r1 = *(const float4*)&red[4];
            float4 r2 = *(const float4*)&red[8];
            float4 r3 = *(const float4*)&red[12];
            float n = fmaxf(fmaxf(fmaxf(r0.x, r0.y), fmaxf(r0.z, r0.w)),
                    fmaxf(fmaxf(fmaxf(r1.x, r1.y), fmaxf(r1.z, r1.w)),
                    fmaxf(fmaxf(fmaxf(r2.x, r2.y), fmaxf(r2.z, r2.w)),
                          fmaxf(fmaxf(r3.x, r3.y), fmaxf(r3.z, r3.w)))));
            scale2 = __fdividef(1.0f, n * TAU_F) * LOG2E_F;
        }

        // ---- Xe = exp2(C*scale2) in registers; frag layout [mi*2+rh][njj] pairs ----
#pragma unroll
        for (int mi = 0; mi < 2; ++mi)
#pragma unroll
            for (int rh = 0; rh < 2; ++rh)
#pragma unroll
                for (int njj = 0; njj < 4; ++njj) {
                    const float* d = acc + (mi * 4 + njj) * 4 + 2 * rh;
                    F2U u;
                    u.f.x = exp2f(d[0] * scale2);
                    u.f.y = exp2f(d[1] * scale2);
                    xe2[(mi * 2 + rh) * 4 + njj] = u.u;
                }
#pragma unroll
        for (int njj = 0; njj < 4; ++njj) rv2[njj] = splat2(1.0f);

        // ---- Sinkhorn: named sub-barriers, parity double-buffered partials ----
        for (int sit = 0; sit < SINK_ITERS; ++sit) {
            float* prow = (float*)(sb + O_PSR) + (sit & 1) * 512;
            float* pcol = (float*)(sb + O_PSC) + (sit & 1) * 512;
#pragma unroll
            for (int mr = 0; mr < 4; ++mr) {
                ull s2 = 0ull;
#pragma unroll
                for (int njj = 0; njj < 4; ++njj) ffma2(s2, xe2[mr * 4 + njj], rv2[njj]);
                F2U u; u.u = s2;
                float s = u.f.x + u.f.y;
                s += __shfl_xor_sync(0xffffffffu, s, 1);
                s += __shfl_xor_sync(0xffffffffu, s, 2);
                if (t4 == 0) {
                    const int r = m0 + 16 * (mr >> 1) + 8 * (mr & 1) + g;
                    prow[r * 4 + (w >> 2)] = s;
                }
            }
            nbar(1 + (w & 3));
#pragma unroll
            for (int mr = 0; mr < 4; ++mr) {
                const int r = m0 + 16 * (mr >> 1) + 8 * (mr & 1) + g;
                float4 v = *(const float4*)&prow[r * 4];
                lu4[mr] = __fdividef(1.0f, (v.x + v.y) + (v.z + v.w));
            }
#pragma unroll
            for (int njj = 0; njj < 4; ++njj) {
                ull cs = 0ull;
#pragma unroll
                for (int mr = 0; mr < 4; ++mr) ffma2(cs, xe2[mr * 4 + njj], splat2(lu4[mr]));
                F2U u; u.u = cs;
                u.f.x += __shfl_xor_sync(0xffffffffu, u.f.x, 4);
                u.f.y += __shfl_xor_sync(0xffffffffu, u.f.y, 4);
                u.f.x += __shfl_xor_sync(0xffffffffu, u.f.x, 8);
                u.f.y += __shfl_xor_sync(0xffffffffu, u.f.y, 8);
                u.f.x += __shfl_xor_sync(0xffffffffu, u.f.x, 16);
                u.f.y += __shfl_xor_sync(0xffffffffu, u.f.y, 16);
                if (lane < 4) {
                    const int c0 = n0 + 8 * njj + 2 * t4;
                    pcol[c0 * 4 + (w & 3)]       = u.f.x;
                    pcol[(c0 + 1) * 4 + (w & 3)] = u.f.y;
                }
            }
            nbar(5 + (w >> 2));
#pragma unroll
            for (int njj = 0; njj < 4; ++njj) {
                const int c0 = n0 + 8 * njj + 2 * t4;
                float4 a0 = *(const float4*)&pcol[c0 * 4];
                float4 a1 = *(const float4*)&pcol[(c0 + 1) * 4];
                F2U u;
                u.f.x = fminf(__fdividef(1.0f, (a0.x + a0.y) + (a0.z + a0.w)), 1.0f);
                u.f.y = fminf(__fdividef(1.0f, (a1.x + a1.y) + (a1.z + a1.w)), 1.0f);
                rv2[njj] = u.u;
            }
        }

        // ---- X_new = lu * Xe * rv^T ----
        if (it + 1 < GROMOV_ITERS) {
#pragma unroll
            for (int mr = 0; mr < 4; ++mr) {
                const ull L = splat2(lu4[mr]);
                u32 xh[4], xl[4];
#pragma unroll
                for (int njj = 0; njj < 4; ++njj) {
                    F2U u; u.u = mul2(mul2(L, xe2[mr * 4 + njj]), rv2[njj]);
                    xh[njj] = cvt2(u.f.y, u.f.x);
                    xl[njj] = lo_residual(xh[njj], u.f.x, u.f.y);
                }
                const u32 ad = stX + (16 * (mr >> 1) + 8 * (mr & 1)) * SB;
                stsm4(ad,      xh[0], xh[1], xh[2], xh[3]);
                stsm4(ad + TS, xl[0], xl[1], xl[2], xl[3]);
            }
        } else {
#pragma unroll
            for (int mr = 0; mr < 4; ++mr) {
                const int r = m0 + 16 * (mr >> 1) + 8 * (mr & 1) + g;
                const ull L = splat2(lu4[mr]);
#pragma unroll
                for (int njj = 0; njj < 4; ++njj) {
                    const int c0 = n0 + 8 * njj + 2 * t4;
                    F2U u; u.u = mul2(mul2(L, xe2[mr * 4 + njj]), rv2[njj]);
                    *(float2*)(outb + r * 128 + c0) = u.f;
                }
            }
        }
    }
}

extern "C" void kernel_launch(void* const* d_in, const int* in_sizes, int n_in,
                              void* d_out, int out_size)
{
    const float* X  = (const float*)d_in[0];
    const float* F1 = (const float*)d_in[1];
    const float* F2 = (const float*)d_in[2];
    const float* Kp = (const float*)d_in[3];
    float* out = (float*)d_out;

    int bs = in_sizes[0] / (128 * 128);
    if (bs > MAXB) bs = MAXB;

    prep_kernel<<<bs, THREADS>>>(F1, F2);

    cudaFuncSetAttribute(gw_kernel, cudaFuncAttributeMaxDynamicSharedMemorySize, SM_TOT);
    gw_kernel<<<bs, THREADS, SM_TOT>>>(X, Kp, out);
}

// round 10
// speedup vs baseline: 2.5390x; 1.0140x over previous
#include <cuda_runtime.h>
#include <cuda_bf16.h>
#include <cstdint>

#define TAU_F 0.1f
#define LOG2E_F 1.44269504f
#define GROMOV_ITERS 15
#define SINK_ITERS 15
#define THREADS 512
#define MAXB 2048
#define SB 272              // smem/global tile row stride (bytes), 128 bf16 cols + pad
#define TS 34816            // tile size bytes = 128*272

typedef unsigned long long ull;
typedef uint32_t u32;

// preconverted bf16 hi/lo tiles per batch: F2H, F2L, F1H, F1L (each TS bytes)
__device__ __align__(16) unsigned char g_tiles[(size_t)MAXB * 4 * TS];

// ---------------- helpers ----------------
__device__ __forceinline__ ull splat2(float x) {
    ull r; asm("mov.b64 %0, {%1, %1};" : "=l"(r) : "f"(x)); return r;
}
__device__ __forceinline__ void ffma2(ull &d, ull a, ull b) {
    asm("fma.rn.f32x2 %0, %1, %2, %0;" : "+l"(d) : "l"(a), "l"(b));
}
__device__ __forceinline__ ull mul2(ull a, ull b) {
    ull d; asm("mul.rn.f32x2 %0, %1, %2;" : "=l"(d) : "l"(a), "l"(b)); return d;
}
union F2U { ull u; float2 f; };
union B2U { __nv_bfloat162 b; u32 u; };

__device__ __forceinline__ void split_bf16(float x, __nv_bfloat16 &h, __nv_bfloat16 &l) {
    h = __float2bfloat16_rn(x);
    l = __float2bfloat16_rn(x - __bfloat162float(h));
}
__device__ __forceinline__ u32 packb(__nv_bfloat16 a, __nv_bfloat16 b) {
    B2U u; u.b = __nv_bfloat162(a, b); return u.u;
}
__device__ __forceinline__ u32 cvt2(float hi, float lo) {
    u32 d; asm("cvt.rn.bf16x2.f32 %0, %1, %2;" : "=r"(d) : "f"(hi), "f"(lo)); return d;
}
__device__ __forceinline__ float bflo(u32 p) { return __uint_as_float(p << 16); }
__device__ __forceinline__ float bfhi(u32 p) { return __uint_as_float(p & 0xFFFF0000u); }
__device__ __forceinline__ u32 lo_residual(u32 hp, float v0, float v1) {
    return cvt2(v1 - bfhi(hp), v0 - bflo(hp));
}

__device__ __forceinline__ u32 smem_u32(const void* p) {
    u32 a; asm("{ .reg .u64 t; cvta.to.shared.u64 t, %1; cvt.u32.u64 %0, t; }" : "=r"(a) : "l"(p));
    return a;
}

__device__ __forceinline__ void ldsm4(u32* r, u32 a) {
    asm volatile("ldmatrix.sync.aligned.m8n8.x4.shared.b16 {%0,%1,%2,%3}, [%4];"
                 : "=r"(r[0]), "=r"(r[1]), "=r"(r[2]), "=r"(r[3]) : "r"(a));
}
__device__ __forceinline__ void ldsm4t(u32* r, u32 a) {
    asm volatile("ldmatrix.sync.aligned.m8n8.x4.trans.shared.b16 {%0,%1,%2,%3}, [%4];"
                 : "=r"(r[0]), "=r"(r[1]), "=r"(r[2]), "=r"(r[3]) : "r"(a));
}
__device__ __forceinline__ void stsm4(u32 a, u32 r0, u32 r1, u32 r2, u32 r3) {
    asm volatile("stmatrix.sync.aligned.m8n8.x4.shared.b16 [%0], {%1,%2,%3,%4};"
                 :: "r"(a), "r"(r0), "r"(r1), "r"(r2), "r"(r3) : "memory");
}
__device__ __forceinline__ void hmma(float* d, u32 a0, u32 a1, u32 a2, u32 a3,
                                     u32 b0, u32 b1) {
    asm volatile("mma.sync.aligned.m16n8k16.row.col.f32.bf16.bf16.f32 "
                 "{%0,%1,%2,%3}, {%4,%5,%6,%7}, {%8,%9}, {%0,%1,%2,%3};"
                 : "+f"(d[0]), "+f"(d[1]), "+f"(d[2]), "+f"(d[3])
                 : "r"(a0), "r"(a1), "r"(a2), "r"(a3), "r"(b0), "r"(b1));
}
__device__ __forceinline__ void mma_blk(float* acc, int njj0, const u32* a8, const u32* b) {
    hmma(acc + (njj0)     * 4, a8[0], a8[1], a8[2], a8[3], b[0], b[1]);
    hmma(acc + (njj0 + 1) * 4, a8[0], a8[1], a8[2], a8[3], b[2], b[3]);
    hmma(acc + (4 + njj0)     * 4, a8[4], a8[5], a8[6], a8[7], b[0], b[1]);
    hmma(acc + (4 + njj0 + 1) * 4, a8[4], a8[5], a8[6], a8[7], b[2], b[3]);
}
// 3-term kk-step with njj-halves interleaved (RAW distance 8 hmma)
__device__ __forceinline__ void mma_step(float* acc, const u32* ah, const u32* al,
                                         const u32* bh, const u32* bl) {
    mma_blk(acc, 0, ah, bh); mma_blk(acc, 2, ah, bh + 4);
    mma_blk(acc, 0, al, bh); mma_blk(acc, 2, al, bh + 4);
    mma_blk(acc, 0, ah, bl); mma_blk(acc, 2, ah, bl + 4);
}

// One single-accumulator GEMM pass, 3-term split (hh + lh + hl).
template<bool AT, bool BT>
__device__ __forceinline__ void gemm_pass(float* acc,
    u32 aH, u32 aL, u32 aStep, u32 aOff2,
    u32 bH, u32 bL, u32 bStep, u32 bOff2)
{
#pragma unroll 2
    for (int kk = 0; kk < 8; ++kk) {
        u32 ah[8], al[8], bh[8], bl[8];
        if (AT) { ldsm4t(ah, aH); ldsm4t(ah + 4, aH + aOff2);
                  ldsm4t(al, aL); ldsm4t(al + 4, aL + aOff2); }
        else    { ldsm4(ah, aH);  ldsm4(ah + 4, aH + aOff2);
                  ldsm4(al, aL);  ldsm4(al + 4, aL + aOff2); }
        if (BT) { ldsm4t(bh, bH); ldsm4t(bh + 4, bH + bOff2);
                  ldsm4t(bl, bL); ldsm4t(bl + 4, bL + bOff2); }
        else    { ldsm4(bh, bH);  ldsm4(bh + 4, bH + bOff2);
                  ldsm4(bl, bL);  ldsm4(bl + 4, bL + bOff2); }
        mma_step(acc, ah, al, bh, bl);
        aH += aStep; aL += aStep; bH += bStep; bL += bStep;
    }
}

#define CP_COMMIT() asm volatile("cp.async.commit_group;" ::: "memory")
#define CP_WAIT0()  asm volatile("cp.async.wait_group 0;" ::: "memory")
__device__ __forceinline__ void cp16(u32 saddr, const void* g) {
    asm volatile("cp.async.cg.shared.global [%0], [%1], 16;" :: "r"(saddr), "l"(g) : "memory");
}
__device__ __forceinline__ void nbar(int id) {
    asm volatile("bar.sync %0, 128;" :: "r"(id) : "memory");
}

// ---------------- smem layout (byte offsets) ----------------
#define O_XH   0
#define O_XL   (TS)
#define O_F2H  (2*TS)       // Z overwrites here after G12; cp.async refills after norm
#define O_F2L  (3*TS)
#define O_F1H  (4*TS)       // loaded once in prologue, never overwritten
#define O_F1L  (5*TS)
#define O_PSR  (6*TS)            // psrow[2][128][8] float (parity double-buffer)
#define O_PSC  (O_PSR + 8192)    // pscol[2][128][4] float
#define O_RED  (O_PSC + 4096)    // red[16] float
#define SM_TOT (O_RED + 128)

// ===================== prep: split F1/F2 to bf16 hi/lo padded tiles =====================
__global__ __launch_bounds__(THREADS, 1)
void prep_kernel(const float* __restrict__ F1g, const float* __restrict__ F2g)
{
    const int t = threadIdx.x, b = blockIdx.x;
    const int row = t >> 2, cb = (t & 3) * 32;
    unsigned char* ob = g_tiles + (size_t)b * 4 * TS;
#pragma unroll
    for (int m = 0; m < 2; ++m) {
        const float* src = (m ? F1g : F2g) + (size_t)b * 16384;
        unsigned char* dH = ob + (size_t)(m ? 2 : 0) * TS + row * SB;
        unsigned char* dL = dH + TS;
#pragma unroll
        for (int q = 0; q < 8; ++q) {
            float4 v = *(const float4*)(src + row * 128 + cb + 4 * q);
            __nv_bfloat16 h0, l0, h1, l1, h2, l2, h3, l3;
            split_bf16(v.x, h0, l0); split_bf16(v.y, h1, l1);
            split_bf16(v.z, h2, l2); split_bf16(v.w, h3, l3);
            *(uint2*)(dH + (cb + 4 * q) * 2) = make_uint2(packb(h0, h1), packb(h2, h3));
            *(uint2*)(dL + (cb + 4 * q) * 2) = make_uint2(packb(l0, l1), packb(l2, l3));
        }
    }
}

// ===================== main kernel =====================
__global__ __launch_bounds__(THREADS, 1)
void gw_kernel(const float* __restrict__ Xg, const float* __restrict__ Kpg,
               float* __restrict__ outg)
{
    extern __shared__ __align__(128) unsigned char sb[];
    const u32 sbu = smem_u32(sb);
    float* red = (float*)(sb + O_RED);

    const int t = threadIdx.x;
    const int w = t >> 5, lane = t & 31;
    const int g = lane >> 2, t4 = lane & 3;
    const int m0 = (w & 3) * 32, n0 = (w >> 2) * 32;
    const int b = blockIdx.x;

    const float* Xb = Xg  + (size_t)b * 16384;
    const float* Kp = Kpg + (size_t)b * 16384;
    float* outb     = outg + (size_t)b * 16384;
    const unsigned char* gb = g_tiles + (size_t)b * 4 * TS;

    // ldmatrix lane-pattern offsets (bytes)
    const int l = lane;
    const u32 pA  = (u32)((l & 15) * SB + ((l >> 4) << 3) * 2);
    const u32 pAT = (u32)(((l & 7) + ((l >> 4) << 3)) * SB + ((l >> 3) & 1) * 16);
    const u32 pBt = (u32)(((l & 7) + (((l >> 3) & 1) << 3)) * SB + ((l >> 4) << 3) * 2);
    const u32 pBn = (u32)(((l & 7) + ((l >> 4) << 3)) * SB + (((l >> 3) & 1) << 3) * 2);

    // warp base addresses
    const u32 aXH  = sbu + O_XH  + m0 * SB + pA;
    const u32 aXL  = sbu + O_XL  + m0 * SB + pA;
    const u32 aF1H = sbu + O_F1H + m0 * SB + pA;
    const u32 aF1L = sbu + O_F1L + m0 * SB + pA;
    const u32 atF1H = sbu + O_F1H + m0 * 2 + pAT;
    const u32 atF1L = sbu + O_F1L + m0 * 2 + pAT;
    const u32 btXH = sbu + O_XH  + n0 * 2 + pBt;   // Y after overwrite
    const u32 btXL = sbu + O_XL  + n0 * 2 + pBt;
    const u32 btF2H = sbu + O_F2H + n0 * 2 + pBt;  // F2 (G12) / Z (G34)
    const u32 btF2L = sbu + O_F2L + n0 * 2 + pBt;
    const u32 bnF2H = sbu + O_F2H + n0 * SB + pBn;
    const u32 bnF2L = sbu + O_F2L + n0 * SB + pBn;

    // stmatrix base (X tile); per (mi,rh) add (16*mi+8*rh)*SB
    const u32 stX = sbu + O_XH + (m0 + (lane & 7)) * SB + (n0 + ((lane >> 3) << 3)) * 2;

    // ---- prologue: X -> bf16 hi/lo tile; prefetch all 4 F tiles ----
    {
        const int row = t >> 2, cb = (t & 3) * 32;
        unsigned char* dH = sb + O_XH + row * SB;
        unsigned char* dL = sb + O_XL + row * SB;
#pragma unroll
        for (int q = 0; q < 8; ++q) {
            float4 v = *(const float4*)(Xb + row * 128 + cb + 4 * q);
            __nv_bfloat16 h0, l0, h1, l1, h2, l2, h3, l3;
            split_bf16(v.x, h0, l0); split_bf16(v.y, h1, l1);
            split_bf16(v.z, h2, l2); split_bf16(v.w, h3, l3);
            *(uint2*)(dH + (cb + 4 * q) * 2) = make_uint2(packb(h0, h1), packb(h2, h3));
            *(uint2*)(dL + (cb + 4 * q) * 2) = make_uint2(packb(l0, l1), packb(l2, l3));
        }
    }
    for (int i = t; i < 4 * TS / 16; i += THREADS)
        cp16(sbu + O_F2H + i * 16, gb + i * 16);
    CP_COMMIT();

    float accY[32], accZ[32], acc[32];
    ull xe2[16], rv2[4];
    float lu4[4];

    for (int it = 0; it < GROMOV_ITERS; ++it) {
        CP_WAIT0();
        __syncthreads();

        // ====== G12: Y = X*F2 (pass 1), Z = X*F2^T (pass 2) ======
#pragma unroll
        for (int q = 0; q < 32; ++q) accY[q] = 0.0f;
        gemm_pass<false, true>(accY, aXH, aXL, 32, 16 * SB,
                               btF2H, btF2L, 16 * SB, 32);
#pragma unroll
        for (int q = 0; q < 32; ++q) accZ[q] = 0.0f;
        gemm_pass<false, false>(accZ, aXH, aXL, 32, 16 * SB,
                                bnF2H, bnF2L, 32, 16 * SB);
        __syncthreads();
        // store Y -> X slots, Z -> F2 slots (bf16 hi/lo via stmatrix)
#pragma unroll
        for (int mi = 0; mi < 2; ++mi)
#pragma unroll
            for (int rh = 0; rh < 2; ++rh) {
                u32 yh[4], yl[4], zh[4], zl[4];
#pragma unroll
                for (int njj = 0; njj < 4; ++njj) {
                    const float* y = accY + (mi * 4 + njj) * 4 + 2 * rh;
                    const float* z = accZ + (mi * 4 + njj) * 4 + 2 * rh;
                    yh[njj] = cvt2(y[1], y[0]);
                    yl[njj] = lo_residual(yh[njj], y[0], y[1]);
                    zh[njj] = cvt2(z[1], z[0]);
                    zl[njj] = lo_residual(zh[njj], z[0], z[1]);
                }
                const u32 ad = stX + (16 * mi + 8 * rh) * SB;
                stsm4(ad,          yh[0], yh[1], yh[2], yh[3]);
                stsm4(ad + TS,     yl[0], yl[1], yl[2], yl[3]);
                stsm4(ad + 2 * TS, zh[0], zh[1], zh[2], zh[3]);
                stsm4(ad + 3 * TS, zl[0], zl[1], zl[2], zl[3]);
            }
        __syncthreads();

        // ====== G34: C = Kp + F1*Y (pass 1) + F1^T*Z (pass 2) ======
#pragma unroll
        for (int mi = 0; mi < 2; ++mi)
#pragma unroll
            for (int njj = 0; njj < 4; ++njj) {
                float* d = acc + (mi * 4 + njj) * 4;
                const int c0 = n0 + 8 * njj + 2 * t4;
                float2 kA = *(const float2*)(Kp + (m0 + 16 * mi + g) * 128 + c0);
                float2 kB = *(const float2*)(Kp + (m0 + 16 * mi + 8 + g) * 128 + c0);
                d[0] = kA.x; d[1] = kA.y; d[2] = kB.x; d[3] = kB.y;
            }
        gemm_pass<false, true>(acc, aF1H, aF1L, 32, 16 * SB,
                               btXH, btXL, 16 * SB, 32);
        gemm_pass<true, true>(acc, atF1H, atF1L, 16 * SB, 32,
                              btF2H, btF2L, 16 * SB, 32);

        // ---- L-inf norm (no extra barrier before; red region disjoint) ----
        float mx = 0.0f;
#pragma unroll
        for (int q = 0; q < 32; ++q) mx = fmaxf(mx, fabsf(acc[q]));
#pragma unroll
        for (int off = 16; off > 0; off >>= 1)
            mx = fmaxf(mx, __shfl_xor_sync(0xffffffffu, mx, off));
        if (lane == 0) red[w] = mx;
        __syncthreads();     // orders G34 reads of F2 tiles before prefetch below
        float scale2;
        {
            float4 r0 = *(const float4*)&red[0];
            float4 r1 = *(const float4*)&red[4];
            float4 r2 = *(const float4*)&red[8];
            float4 r3 = *(const float4*)&red[12];
            float n = fmaxf(fmaxf(fmaxf(r0.x, r0.y), fmaxf(r0.z, r0.w)),
                    fmaxf(fmaxf(fmaxf(r1.x, r1.y), fmaxf(r1.z, r1.w)),
                    fmaxf(fmaxf(fmaxf(r2.x, r2.y), fmaxf(r2.z, r2.w)),
                          fmaxf(fmaxf(r3.x, r3.y), fmaxf(r3.z, r3.w)))));
            scale2 = __fdividef(1.0f, n * TAU_F) * LOG2E_F;
        }

        // prefetch next iter's F2 (overlaps all of Sinkhorn)
        if (it + 1 < GROMOV_ITERS) {
            for (int i = t; i < 2 * TS / 16; i += THREADS)
                cp16(sbu + O_F2H + i * 16, gb + i * 16);
            CP_COMMIT();
        }

        // ---- Xe = exp2(C*scale2) in registers; frag layout [mi*2+rh][njj] pairs ----
#pragma unroll
        for (int mi = 0; mi < 2; ++mi)
#pragma unroll
            for (int rh = 0; rh < 2; ++rh)
#pragma unroll
                for (int njj = 0; njj < 4; ++njj) {
                    const float* d = acc + (mi * 4 + njj) * 4 + 2 * rh;
                    F2U u;
                    u.f.x = exp2f(d[0] * scale2);
                    u.f.y = exp2f(d[1] * scale2);
                    xe2[(mi * 2 + rh) * 4 + njj] = u.u;
                }
#pragma unroll
        for (int njj = 0; njj < 4; ++njj) rv2[njj] = splat2(1.0f);

        // ---- Sinkhorn: named sub-barriers, parity double-buffered partials ----
        for (int sit = 0; sit < SINK_ITERS; ++sit) {
            float* prow = (float*)(sb + O_PSR) + (sit & 1) * 1024;
            float* pcol = (float*)(sb + O_PSC) + (sit & 1) * 512;
#pragma unroll
            for (int mr = 0; mr < 4; ++mr) {
                ull s2 = 0ull;
#pragma unroll
                for (int njj = 0; njj < 4; ++njj) ffma2(s2, xe2[mr * 4 + njj], rv2[njj]);
                F2U u; u.u = s2;
                float s = u.f.x + u.f.y;
                s += __shfl_xor_sync(0xffffffffu, s, 1);
                if ((t4 & 1) == 0) {
                    const int r = m0 + 16 * (mr >> 1) + 8 * (mr & 1) + g;
                    prow[r * 8 + (w >> 2) * 2 + (t4 >> 1)] = s;
                }
            }
            nbar(1 + (w & 3));
#pragma unroll
            for (int mr = 0; mr < 4; ++mr) {
                const int r = m0 + 16 * (mr >> 1) + 8 * (mr & 1) + g;
                float4 v0 = *(const float4*)&prow[r * 8];
                float4 v1 = *(const float4*)&prow[r * 8 + 4];
                lu4[mr] = __fdividef(1.0f,
                    ((v0.x + v0.y) + (v0.z + v0.w)) + ((v1.x + v1.y) + (v1.z + v1.w)));
            }
#pragma unroll
            for (int njj = 0; njj < 4; ++njj) {
                ull cs = 0ull;
#pragma unroll
                for (int mr = 0; mr < 4; ++mr) ffma2(cs, xe2[mr * 4 + njj], splat2(lu4[mr]));
                F2U u; u.u = cs;
                u.f.x += __shfl_xor_sync(0xffffffffu, u.f.x, 4);
                u.f.y += __shfl_xor_sync(0xffffffffu, u.f.y, 4);
                u.f.x += __shfl_xor_sync(0xffffffffu, u.f.x, 8);
                u.f.y += __shfl_xor_sync(0xffffffffu, u.f.y, 8);
                u.f.x += __shfl_xor_sync(0xffffffffu, u.f.x, 16);
                u.f.y += __shfl_xor_sync(0xffffffffu, u.f.y, 16);
                if (lane < 4) {
                    const int c0 = n0 + 8 * njj + 2 * t4;
                    pcol[c0 * 4 + (w & 3)]       = u.f.x;
                    pcol[(c0 + 1) * 4 + (w & 3)] = u.f.y;
                }
            }
            nbar(5 + (w >> 2));
#pragma unroll
            for (int njj = 0; njj < 4; ++njj) {
                const int c0 = n0 + 8 * njj + 2 * t4;
                float4 a0 = *(const float4*)&pcol[c0 * 4];
                float4 a1 = *(const float4*)&pcol[(c0 + 1) * 4];
                F2U u;
                u.f.x = fminf(__fdividef(1.0f, (a0.x + a0.y) + (a0.z + a0.w)), 1.0f);
                u.f.y = fminf(__fdividef(1.0f, (a1.x + a1.y) + (a1.z + a1.w)), 1.0f);
                rv2[njj] = u.u;
            }
        }

        // ---- X_new = lu * Xe * rv^T ----
        if (it + 1 < GROMOV_ITERS) {
#pragma unroll
            for (int mr = 0; mr < 4; ++mr) {
                const ull L = splat2(lu4[mr]);
                u32 xh[4], xl[4];
#pragma unroll
                for (int njj = 0; njj < 4; ++njj) {
                    F2U u; u.u = mul2(mul2(L, xe2[mr * 4 + njj]), rv2[njj]);
                    xh[njj] = cvt2(u.f.y, u.f.x);
                    xl[njj] = lo_residual(xh[njj], u.f.x, u.f.y);
                }
                const u32 ad = stX + (16 * (mr >> 1) + 8 * (mr & 1)) * SB;
                stsm4(ad,      xh[0], xh[1], xh[2], xh[3]);
                stsm4(ad + TS, xl[0], xl[1], xl[2], xl[3]);
            }
        } else {
#pragma unroll
            for (int mr = 0; mr < 4; ++mr) {
                const int r = m0 + 16 * (mr >> 1) + 8 * (mr & 1) + g;
                const ull L = splat2(lu4[mr]);
#pragma unroll
                for (int njj = 0; njj < 4; ++njj) {
                    const int c0 = n0 + 8 * njj + 2 * t4;
                    F2U u; u.u = mul2(mul2(L, xe2[mr * 4 + njj]), rv2[njj]);
                    *(float2*)(outb + r * 128 + c0) = u.f;
                }
            }
        }
    }
}

extern "C" void kernel_launch(void* const* d_in, const int* in_sizes, int n_in,
                              void* d_out, int out_size)
{
    const float* X  = (const float*)d_in[0];
    const float* F1 = (const float*)d_in[1];
    const float* F2 = (const float*)d_in[2];
    const float* Kp = (const float*)d_in[3];
    float* out = (float*)d_out;

    int bs = in_sizes[0] / (128 * 128);
    if (bs > MAXB) bs = MAXB;

    prep_kernel<<<bs, THREADS>>>(F1, F2);

    cudaFuncSetAttribute(gw_kernel, cudaFuncAttributeMaxDynamicSharedMemorySize, SM_TOT);
    gw_kernel<<<bs, THREADS, SM_TOT>>>(X, Kp, out);
}